// round 5
// baseline (speedup 1.0000x reference)
#include <cuda_runtime.h>
#include <cuda_bf16.h>
#include <cstdint>

// ============================================================================
// out[i] = W2 @ relu(W1 @ x_i + b1) + b2  for i >= 4
// rows 0..3 all equal W2 @ relu(W1 @ mean(x_0..3) + b1) + b2
//
// Single fused kernel, mma.sync m16n8k16 bf16, 3-pass error-compensated split.
// Each warp processes 32 rows (two 16-row strips) sharing B fragments ->
// halves LDSM traffic (L1tex was the binding pipe at 86%).
// ============================================================================

#define TM       512      // rows per CTA
#define THREADS  512      // 16 warps x 32 rows

// smem layout (bytes)
#define S_W1     272
#define S_W2     144
#define OFF_W1HI 0
#define OFF_W1LO 17408
#define OFF_W2HI 34816
#define OFF_W2LO 44032
#define WBYTES   53248

__device__ __forceinline__ uint32_t smem_u32(const void* p) {
    uint32_t a;
    asm("{ .reg .u64 t; cvta.to.shared.u64 t, %1; cvt.u32.u64 %0, t; }"
        : "=r"(a) : "l"(p));
    return a;
}

// truncation split: hi = top 16 bits of each fp32, lo = rn(x - hi)
__device__ __forceinline__ void split_pack(float x0, float x1,
                                           uint32_t& hi, uint32_t& lo) {
    uint32_t b0 = __float_as_uint(x0), b1 = __float_as_uint(x1);
    asm("prmt.b32 %0, %1, %2, 0x7632;" : "=r"(hi) : "r"(b0), "r"(b1));
    float r0 = x0 - __uint_as_float(b0 & 0xFFFF0000u);
    float r1 = x1 - __uint_as_float(b1 & 0xFFFF0000u);
    asm("cvt.rn.bf16x2.f32 %0, %1, %2;" : "=r"(lo) : "f"(r1), "f"(r0));
}

__device__ __forceinline__ void ldsm4(uint32_t* r, uint32_t addr) {
    asm volatile("ldmatrix.sync.aligned.m8n8.x4.shared.b16 {%0,%1,%2,%3}, [%4];"
                 : "=r"(r[0]), "=r"(r[1]), "=r"(r[2]), "=r"(r[3])
                 : "r"(addr));
}

__device__ __forceinline__ void mma_bf16(float* d, const uint32_t* a,
                                         uint32_t b0, uint32_t b1) {
    asm volatile(
        "mma.sync.aligned.m16n8k16.row.col.f32.bf16.bf16.f32 "
        "{%0,%1,%2,%3}, {%4,%5,%6,%7}, {%8,%9}, {%0,%1,%2,%3};"
        : "+f"(d[0]), "+f"(d[1]), "+f"(d[2]), "+f"(d[3])
        : "r"(a[0]), "r"(a[1]), "r"(a[2]), "r"(a[3]), "r"(b0), "r"(b1));
}

// epilogue1 + GEMM2 + store for one 16-row strip (keeps liveness bounded)
__device__ __forceinline__ void gemm2_store(
    const float acc[8][4], const float* __restrict__ b1,
    const float* __restrict__ b2, float* __restrict__ out,
    long orow, bool st0, bool st8, int q,
    uint32_t aW2hi, uint32_t aW2lo) {
    // H = relu(acc + b1), split to bf16 frags (registers only)
    uint32_t hhr[8], hhr8[8], hlr[8], hlr8[8];
#pragma unroll
    for (int j = 0; j < 8; j++) {
        float2 bv = *(const float2*)(b1 + j * 8 + q * 2);
        float h00 = fmaxf(acc[j][0] + bv.x, 0.f);
        float h01 = fmaxf(acc[j][1] + bv.y, 0.f);
        float h10 = fmaxf(acc[j][2] + bv.x, 0.f);
        float h11 = fmaxf(acc[j][3] + bv.y, 0.f);
        split_pack(h00, h01, hhr[j],  hlr[j]);
        split_pack(h10, h11, hhr8[j], hlr8[j]);
    }

    float acc2[8][4];
#pragma unroll
    for (int j = 0; j < 8; j++)
#pragma unroll
        for (int i = 0; i < 4; i++) acc2[j][i] = 0.f;

#pragma unroll
    for (int t = 0; t < 4; t++) {
        uint32_t ah[4] = {hhr[2*t], hhr8[2*t], hhr[2*t+1], hhr8[2*t+1]};
        uint32_t al[4] = {hlr[2*t], hlr8[2*t], hlr[2*t+1], hlr8[2*t+1]};
#pragma unroll
        for (int j = 0; j < 4; j++) {
            uint32_t bh[4], bl[4];
            ldsm4(bh, aW2hi + j * (16 * S_W2) + t * 32);
            ldsm4(bl, aW2lo + j * (16 * S_W2) + t * 32);
            mma_bf16(acc2[2*j],   ah, bh[0], bh[1]);
            mma_bf16(acc2[2*j],   ah, bl[0], bl[1]);
            mma_bf16(acc2[2*j],   al, bh[0], bh[1]);
            mma_bf16(acc2[2*j+1], ah, bh[2], bh[3]);
            mma_bf16(acc2[2*j+1], ah, bl[2], bl[3]);
            mma_bf16(acc2[2*j+1], al, bh[2], bh[3]);
        }
    }

#pragma unroll
    for (int j = 0; j < 8; j++) {
        float2 bv = *(const float2*)(b2 + j * 8 + q * 2);
        if (st0) {
            float2 o = make_float2(acc2[j][0] + bv.x, acc2[j][1] + bv.y);
            *(float2*)(out + orow * 64 + j * 8 + q * 2) = o;
        }
        if (st8) {
            float2 o = make_float2(acc2[j][2] + bv.x, acc2[j][3] + bv.y);
            *(float2*)(out + (orow + 8) * 64 + j * 8 + q * 2) = o;
        }
    }
}

__global__ void __launch_bounds__(THREADS, 1)
mlp_main(const float* __restrict__ audio, const float* __restrict__ video,
         const float* __restrict__ x1,    const float* __restrict__ x2,
         const float* __restrict__ W1,    const float* __restrict__ b1,
         const float* __restrict__ W2,    const float* __restrict__ b2,
         float* __restrict__ out, long nrows) {
    extern __shared__ char smem[];
    const uint32_t sb = smem_u32(smem);
    const int tid = threadIdx.x;

    // ---- stage 0: load fp32 weights, split to bf16 hi/lo in smem ----
    {
        const float4* W1f4 = (const float4*)W1;   // 2048 float4
        const float4* W2f4 = (const float4*)W2;   // 1024 float4
#pragma unroll
        for (int it = 0; it < 6; it++) {          // 3072 float4 total
            int i = tid + it * THREADS;
            float4 v;
            uint32_t off_hi, off_lo;
            if (i < 2048) {
                v = W1f4[i];
                int n = i >> 5, k4 = i & 31;
                off_hi = OFF_W1HI + n * S_W1 + k4 * 8;
                off_lo = OFF_W1LO + n * S_W1 + k4 * 8;
            } else {
                int j = i - 2048;
                v = W2f4[j];
                int n = j >> 4, k4 = j & 15;
                off_hi = OFF_W2HI + n * S_W2 + k4 * 8;
                off_lo = OFF_W2LO + n * S_W2 + k4 * 8;
            }
            uint2 hp, lp;
            split_pack(v.x, v.y, hp.x, lp.x);
            split_pack(v.z, v.w, hp.y, lp.y);
            *(uint2*)(smem + off_hi) = hp;
            *(uint2*)(smem + off_lo) = lp;
        }
    }
    __syncthreads();

    const int wid  = tid >> 5;
    const int lane = tid & 31;
    const int r = lane >> 2;      // fragment row 0..7
    const int q = lane & 3;       // fragment col quad

    const long row0 = (long)blockIdx.x * TM;
    const long orow = row0 + wid * 32 + r;     // strip0 rows: orow, orow+8
    const bool full = (row0 + TM) <= nrows;    // strip1 rows: +16, +24
    long lr[4];                                 // clamped load rows
#pragma unroll
    for (int s = 0; s < 4; s++) {
        long rr = orow + s * 8;
        if (!full) { long mx = nrows - 1; rr = rr < mx ? rr : mx; }
        lr[s] = rr;
    }

    // per-lane ldmatrix base offsets
    const int rowp = ((lane >> 4) & 1) * 8 + (lane & 7);
    const int kadd = ((lane >> 3) & 1) * 16;
    const uint32_t aW1hi = sb + OFF_W1HI + rowp * S_W1 + kadd;
    const uint32_t aW1lo = sb + OFF_W1LO + rowp * S_W1 + kadd;
    const uint32_t aW2hi = sb + OFF_W2HI + rowp * S_W2 + kadd;
    const uint32_t aW2lo = sb + OFF_W2LO + rowp * S_W2 + kadd;

    const float* mods[4] = {audio, video, x1, x2};

    // ---- GEMM1: two strips, B fragments shared ----
    float acc0[8][4], acc1[8][4];
#pragma unroll
    for (int j = 0; j < 8; j++)
#pragma unroll
        for (int i = 0; i < 4; i++) { acc0[j][i] = 0.f; acc1[j][i] = 0.f; }

    // prefetch kt=0 (8 float2: 4 rows x 2 col-halves)
    float2 p[4][2];
    {
        const float* pm = mods[0];
        const int co = q * 2;
#pragma unroll
        for (int s = 0; s < 4; s++) {
            p[s][0] = *(const float2*)(pm + lr[s] * 32 + co);
            p[s][1] = *(const float2*)(pm + lr[s] * 32 + co + 8);
        }
    }

#pragma unroll
    for (int kt = 0; kt < 8; kt++) {
        float2 nx[4][2];
        if (kt < 7) {
            const float* pm = mods[(kt + 1) >> 1];
            const int co = ((kt + 1) & 1) * 16 + q * 2;
#pragma unroll
            for (int s = 0; s < 4; s++) {
                nx[s][0] = *(const float2*)(pm + lr[s] * 32 + co);
                nx[s][1] = *(const float2*)(pm + lr[s] * 32 + co + 8);
            }
        }

        uint32_t ah0[4], al0[4], ah1[4], al1[4];
        split_pack(p[0][0].x, p[0][0].y, ah0[0], al0[0]);
        split_pack(p[1][0].x, p[1][0].y, ah0[1], al0[1]);
        split_pack(p[0][1].x, p[0][1].y, ah0[2], al0[2]);
        split_pack(p[1][1].x, p[1][1].y, ah0[3], al0[3]);
        split_pack(p[2][0].x, p[2][0].y, ah1[0], al1[0]);
        split_pack(p[3][0].x, p[3][0].y, ah1[1], al1[1]);
        split_pack(p[2][1].x, p[2][1].y, ah1[2], al1[2]);
        split_pack(p[3][1].x, p[3][1].y, ah1[3], al1[3]);

#pragma unroll
        for (int j = 0; j < 4; j++) {
            uint32_t bh[4], bl[4];
            ldsm4(bh, aW1hi + j * (16 * S_W1) + kt * 32);
            ldsm4(bl, aW1lo + j * (16 * S_W1) + kt * 32);
            mma_bf16(acc0[2*j],   ah0, bh[0], bh[1]);
            mma_bf16(acc0[2*j],   ah0, bl[0], bl[1]);
            mma_bf16(acc0[2*j],   al0, bh[0], bh[1]);
            mma_bf16(acc0[2*j+1], ah0, bh[2], bh[3]);
            mma_bf16(acc0[2*j+1], ah0, bl[2], bl[3]);
            mma_bf16(acc0[2*j+1], al0, bh[2], bh[3]);
            mma_bf16(acc1[2*j],   ah1, bh[0], bh[1]);
            mma_bf16(acc1[2*j],   ah1, bl[0], bl[1]);
            mma_bf16(acc1[2*j],   al1, bh[0], bh[1]);
            mma_bf16(acc1[2*j+1], ah1, bh[2], bh[3]);
            mma_bf16(acc1[2*j+1], ah1, bl[2], bl[3]);
            mma_bf16(acc1[2*j+1], al1, bh[2], bh[3]);
        }
#pragma unroll
        for (int s = 0; s < 4; s++) { p[s][0] = nx[s][0]; p[s][1] = nx[s][1]; }
    }

    // ---- strip 0: epilogue + GEMM2 + store (acc1 stays live) ----
    {
        const bool st0 = full || (orow     < nrows);
        const bool st8 = full || (orow + 8 < nrows);
        gemm2_store(acc0, b1, b2, out, orow, st0, st8, q, aW2hi, aW2lo);
    }
    // ---- strip 1 ----
    {
        const bool st0 = full || (orow + 16 < nrows);
        const bool st8 = full || (orow + 24 < nrows);
        gemm2_store(acc1, b1, b2, out, orow + 16, st0, st8, q, aW2hi, aW2lo);
    }

    // ---- block 0: exact fp32 fixup for graph rows 0..3 ----
    if (blockIdx.x == 0) {
        __syncthreads();                 // rows 0..3 stored above by this block
        float* xbar = (float*)smem;      // weights in smem are dead now
        float* h    = xbar + 128;
        const int t = tid;
        if (t < 128) {
            const float* pm = mods[t >> 5];
            int c = t & 31;
            xbar[t] = 0.25f * (pm[c] + pm[32 + c] + pm[64 + c] + pm[96 + c]);
        }
        __syncthreads();
        if (t < 64) {
            float s = 0.f;
            const float* wr = &W1[t * 128];
#pragma unroll 8
            for (int k = 0; k < 128; k++) s = fmaf(wr[k], xbar[k], s);
            h[t] = fmaxf(s + b1[t], 0.f);
        }
        __syncthreads();
        if (t < 64) {
            float s = 0.f;
            const float* wr = &W2[t * 64];
#pragma unroll 8
            for (int j = 0; j < 64; j++) s = fmaf(wr[j], h[j], s);
            float v = s + b2[t];
            out[0 * 64 + t] = v;
            out[1 * 64 + t] = v;
            out[2 * 64 + t] = v;
            out[3 * 64 + t] = v;
        }
    }
}

extern "C" void kernel_launch(void* const* d_in, const int* in_sizes, int n_in,
                              void* d_out, int out_size) {
    const float* audio = (const float*)d_in[0];
    const float* video = (const float*)d_in[1];
    const float* x1    = (const float*)d_in[2];
    const float* x2    = (const float*)d_in[3];
    const float* W1    = (const float*)d_in[4];
    const float* b1    = (const float*)d_in[5];
    const float* W2    = (const float*)d_in[6];
    const float* b2    = (const float*)d_in[7];
    float* out = (float*)d_out;

    long nrows = (long)(in_sizes[0] / 32);
    int grid = (int)((nrows + TM - 1) / TM);

    cudaFuncSetAttribute(mlp_main, cudaFuncAttributeMaxDynamicSharedMemorySize,
                         WBYTES);

    mlp_main<<<grid, THREADS, WBYTES>>>(audio, video, x1, x2, W1, b1, W2, b2,
                                        out, nrows);
}

// round 6
// speedup vs baseline: 1.1902x; 1.1902x over previous
#include <cuda_runtime.h>
#include <cuda_fp16.h>
#include <cstdint>

// ============================================================================
// out[i] = W2 @ relu(W1 @ x_i + b1) + b2  for i >= 4
// rows 0..3 all equal W2 @ relu(W1 @ mean(x_0..3) + b1) + b2
//
// mma.sync m16n8k16 fp16 (fp32 accum). Accuracy: A (activations) single
// rn-fp16 (err ~2^-11); B (weights) split hi+lo fp16 -> 2 MMA passes.
// Predicted rel_err ~4e-4 (norm ratio) vs 1e-3 threshold.
// ============================================================================

#define TM       512      // rows per CTA
#define THREADS  512      // 16 warps x 32 rows

// smem layout (bytes)
#define S_W1     272
#define S_W2     144
#define OFF_W1HI 0
#define OFF_W1LO 17408
#define OFF_W2HI 34816
#define OFF_W2LO 44032
#define WBYTES   53248

__device__ __forceinline__ uint32_t smem_u32(const void* p) {
    uint32_t a;
    asm("{ .reg .u64 t; cvta.to.shared.u64 t, %1; cvt.u32.u64 %0, t; }"
        : "=r"(a) : "l"(p));
    return a;
}

// pack two fp32 -> f16x2 (x0 in low half)
__device__ __forceinline__ uint32_t pack_f16(float x0, float x1) {
    uint32_t r;
    asm("cvt.rn.f16x2.f32 %0, %1, %2;" : "=r"(r) : "f"(x1), "f"(x0));
    return r;
}

__device__ __forceinline__ void ldsm4(uint32_t* r, uint32_t addr) {
    asm volatile("ldmatrix.sync.aligned.m8n8.x4.shared.b16 {%0,%1,%2,%3}, [%4];"
                 : "=r"(r[0]), "=r"(r[1]), "=r"(r[2]), "=r"(r[3])
                 : "r"(addr));
}

__device__ __forceinline__ void mma_f16(float* d, const uint32_t* a,
                                        uint32_t b0, uint32_t b1) {
    asm volatile(
        "mma.sync.aligned.m16n8k16.row.col.f32.f16.f16.f32 "
        "{%0,%1,%2,%3}, {%4,%5,%6,%7}, {%8,%9}, {%0,%1,%2,%3};"
        : "+f"(d[0]), "+f"(d[1]), "+f"(d[2]), "+f"(d[3])
        : "r"(a[0]), "r"(a[1]), "r"(a[2]), "r"(a[3]), "r"(b0), "r"(b1));
}

// epilogue1 + GEMM2 + store for one 16-row strip
__device__ __forceinline__ void gemm2_store(
    const float acc[8][4], const float* __restrict__ b1,
    const float* __restrict__ b2, float* __restrict__ out,
    long orow, bool st0, bool st8, int q,
    uint32_t aW2hi, uint32_t aW2lo) {
    // H = relu(acc + b1) -> fp16 fragments (registers only)
    uint32_t hr[8], hr8[8];
#pragma unroll
    for (int j = 0; j < 8; j++) {
        float2 bv = *(const float2*)(b1 + j * 8 + q * 2);
        float h00 = fmaxf(acc[j][0] + bv.x, 0.f);
        float h01 = fmaxf(acc[j][1] + bv.y, 0.f);
        float h10 = fmaxf(acc[j][2] + bv.x, 0.f);
        float h11 = fmaxf(acc[j][3] + bv.y, 0.f);
        hr[j]  = pack_f16(h00, h01);
        hr8[j] = pack_f16(h10, h11);
    }

    float acc2[8][4];
#pragma unroll
    for (int j = 0; j < 8; j++)
#pragma unroll
        for (int i = 0; i < 4; i++) acc2[j][i] = 0.f;

#pragma unroll
    for (int t = 0; t < 4; t++) {
        uint32_t ah[4] = {hr[2*t], hr8[2*t], hr[2*t+1], hr8[2*t+1]};
#pragma unroll
        for (int j = 0; j < 4; j++) {
            uint32_t bh[4], bl[4];
            ldsm4(bh, aW2hi + j * (16 * S_W2) + t * 32);
            ldsm4(bl, aW2lo + j * (16 * S_W2) + t * 32);
            mma_f16(acc2[2*j],   ah, bh[0], bh[1]);
            mma_f16(acc2[2*j],   ah, bl[0], bl[1]);
            mma_f16(acc2[2*j+1], ah, bh[2], bh[3]);
            mma_f16(acc2[2*j+1], ah, bl[2], bl[3]);
        }
    }

#pragma unroll
    for (int j = 0; j < 8; j++) {
        float2 bv = *(const float2*)(b2 + j * 8 + q * 2);
        if (st0) {
            float2 o = make_float2(acc2[j][0] + bv.x, acc2[j][1] + bv.y);
            *(float2*)(out + orow * 64 + j * 8 + q * 2) = o;
        }
        if (st8) {
            float2 o = make_float2(acc2[j][2] + bv.x, acc2[j][3] + bv.y);
            *(float2*)(out + (orow + 8) * 64 + j * 8 + q * 2) = o;
        }
    }
}

__global__ void __launch_bounds__(THREADS, 1)
mlp_main(const float* __restrict__ audio, const float* __restrict__ video,
         const float* __restrict__ x1,    const float* __restrict__ x2,
         const float* __restrict__ W1,    const float* __restrict__ b1,
         const float* __restrict__ W2,    const float* __restrict__ b2,
         float* __restrict__ out, long nrows) {
    extern __shared__ char smem[];
    const uint32_t sb = smem_u32(smem);
    const int tid = threadIdx.x;

    // ---- stage 0: load fp32 weights, split to fp16 hi + residual lo ----
    {
        const float4* W1f4 = (const float4*)W1;   // 2048 float4
        const float4* W2f4 = (const float4*)W2;   // 1024 float4
#pragma unroll
        for (int it = 0; it < 6; it++) {          // 3072 float4 total
            int i = tid + it * THREADS;
            float4 v;
            uint32_t off_hi, off_lo;
            if (i < 2048) {
                v = W1f4[i];
                int n = i >> 5, k4 = i & 31;
                off_hi = OFF_W1HI + n * S_W1 + k4 * 8;
                off_lo = OFF_W1LO + n * S_W1 + k4 * 8;
            } else {
                int j = i - 2048;
                v = W2f4[j];
                int n = j >> 4, k4 = j & 15;
                off_hi = OFF_W2HI + n * S_W2 + k4 * 8;
                off_lo = OFF_W2LO + n * S_W2 + k4 * 8;
            }
            uint2 hp, lp;
            hp.x = pack_f16(v.x, v.y);
            hp.y = pack_f16(v.z, v.w);
            __half2 h0 = *(__half2*)&hp.x;
            __half2 h1 = *(__half2*)&hp.y;
            lp.x = pack_f16(v.x - __low2float(h0), v.y - __high2float(h0));
            lp.y = pack_f16(v.z - __low2float(h1), v.w - __high2float(h1));
            *(uint2*)(smem + off_hi) = hp;
            *(uint2*)(smem + off_lo) = lp;
        }
    }
    __syncthreads();

    const int wid  = tid >> 5;
    const int lane = tid & 31;
    const int r = lane >> 2;      // fragment row 0..7
    const int q = lane & 3;       // fragment col quad

    const long row0 = (long)blockIdx.x * TM;
    const long orow = row0 + wid * 32 + r;     // strip0 rows: orow, orow+8
    const bool full = (row0 + TM) <= nrows;    // strip1 rows: +16, +24
    long lr[4];
#pragma unroll
    for (int s = 0; s < 4; s++) {
        long rr = orow + s * 8;
        if (!full) { long mx = nrows - 1; rr = rr < mx ? rr : mx; }
        lr[s] = rr;
    }

    // per-lane ldmatrix base offsets
    const int rowp = ((lane >> 4) & 1) * 8 + (lane & 7);
    const int kadd = ((lane >> 3) & 1) * 16;
    const uint32_t aW1hi = sb + OFF_W1HI + rowp * S_W1 + kadd;
    const uint32_t aW1lo = sb + OFF_W1LO + rowp * S_W1 + kadd;
    const uint32_t aW2hi = sb + OFF_W2HI + rowp * S_W2 + kadd;
    const uint32_t aW2lo = sb + OFF_W2LO + rowp * S_W2 + kadd;

    const float* mods[4] = {audio, video, x1, x2};

    // ---- GEMM1: two 16-row strips share B fragments ----
    float acc0[8][4], acc1[8][4];
#pragma unroll
    for (int j = 0; j < 8; j++)
#pragma unroll
        for (int i = 0; i < 4; i++) { acc0[j][i] = 0.f; acc1[j][i] = 0.f; }

    float2 p[4][2];
    {
        const float* pm = mods[0];
        const int co = q * 2;
#pragma unroll
        for (int s = 0; s < 4; s++) {
            p[s][0] = *(const float2*)(pm + lr[s] * 32 + co);
            p[s][1] = *(const float2*)(pm + lr[s] * 32 + co + 8);
        }
    }

#pragma unroll
    for (int kt = 0; kt < 8; kt++) {
        float2 nx[4][2];
        if (kt < 7) {
            const float* pm = mods[(kt + 1) >> 1];
            const int co = ((kt + 1) & 1) * 16 + q * 2;
#pragma unroll
            for (int s = 0; s < 4; s++) {
                nx[s][0] = *(const float2*)(pm + lr[s] * 32 + co);
                nx[s][1] = *(const float2*)(pm + lr[s] * 32 + co + 8);
            }
        }

        uint32_t ah0[4], ah1[4];
        ah0[0] = pack_f16(p[0][0].x, p[0][0].y);
        ah0[1] = pack_f16(p[1][0].x, p[1][0].y);
        ah0[2] = pack_f16(p[0][1].x, p[0][1].y);
        ah0[3] = pack_f16(p[1][1].x, p[1][1].y);
        ah1[0] = pack_f16(p[2][0].x, p[2][0].y);
        ah1[1] = pack_f16(p[3][0].x, p[3][0].y);
        ah1[2] = pack_f16(p[2][1].x, p[2][1].y);
        ah1[3] = pack_f16(p[3][1].x, p[3][1].y);

#pragma unroll
        for (int j = 0; j < 4; j++) {
            uint32_t bh[4], bl[4];
            ldsm4(bh, aW1hi + j * (16 * S_W1) + kt * 32);
            ldsm4(bl, aW1lo + j * (16 * S_W1) + kt * 32);
            mma_f16(acc0[2*j],   ah0, bh[0], bh[1]);
            mma_f16(acc0[2*j],   ah0, bl[0], bl[1]);
            mma_f16(acc0[2*j+1], ah0, bh[2], bh[3]);
            mma_f16(acc0[2*j+1], ah0, bl[2], bl[3]);
            mma_f16(acc1[2*j],   ah1, bh[0], bh[1]);
            mma_f16(acc1[2*j],   ah1, bl[0], bl[1]);
            mma_f16(acc1[2*j+1], ah1, bh[2], bh[3]);
            mma_f16(acc1[2*j+1], ah1, bl[2], bl[3]);
        }
#pragma unroll
        for (int s = 0; s < 4; s++) { p[s][0] = nx[s][0]; p[s][1] = nx[s][1]; }
    }

    // ---- strip 0, then strip 1 ----
    {
        const bool st0 = full || (orow     < nrows);
        const bool st8 = full || (orow + 8 < nrows);
        gemm2_store(acc0, b1, b2, out, orow, st0, st8, q, aW2hi, aW2lo);
    }
    {
        const bool st0 = full || (orow + 16 < nrows);
        const bool st8 = full || (orow + 24 < nrows);
        gemm2_store(acc1, b1, b2, out, orow + 16, st0, st8, q, aW2hi, aW2lo);
    }

    // ---- block 0: exact fp32 fixup for graph rows 0..3 ----
    if (blockIdx.x == 0) {
        __syncthreads();
        float* xbar = (float*)smem;      // weights in smem are dead now
        float* h    = xbar + 128;
        const int t = tid;
        if (t < 128) {
            const float* pm = mods[t >> 5];
            int c = t & 31;
            xbar[t] = 0.25f * (pm[c] + pm[32 + c] + pm[64 + c] + pm[96 + c]);
        }
        __syncthreads();
        if (t < 64) {
            float s = 0.f;
            const float* wr = &W1[t * 128];
#pragma unroll 8
            for (int k = 0; k < 128; k++) s = fmaf(wr[k], xbar[k], s);
            h[t] = fmaxf(s + b1[t], 0.f);
        }
        __syncthreads();
        if (t < 64) {
            float s = 0.f;
            const float* wr = &W2[t * 64];
#pragma unroll 8
            for (int j = 0; j < 64; j++) s = fmaf(wr[j], h[j], s);
            float v = s + b2[t];
            out[0 * 64 + t] = v;
            out[1 * 64 + t] = v;
            out[2 * 64 + t] = v;
            out[3 * 64 + t] = v;
        }
    }
}

extern "C" void kernel_launch(void* const* d_in, const int* in_sizes, int n_in,
                              void* d_out, int out_size) {
    const float* audio = (const float*)d_in[0];
    const float* video = (const float*)d_in[1];
    const float* x1    = (const float*)d_in[2];
    const float* x2    = (const float*)d_in[3];
    const float* W1    = (const float*)d_in[4];
    const float* b1    = (const float*)d_in[5];
    const float* W2    = (const float*)d_in[6];
    const float* b2    = (const float*)d_in[7];
    float* out = (float*)d_out;

    long nrows = (long)(in_sizes[0] / 32);
    int grid = (int)((nrows + TM - 1) / TM);

    cudaFuncSetAttribute(mlp_main, cudaFuncAttributeMaxDynamicSharedMemorySize,
                         WBYTES);

    mlp_main<<<grid, THREADS, WBYTES>>>(audio, video, x1, x2, W1, b1, W2, b2,
                                        out, nrows);
}

// round 8
// speedup vs baseline: 1.3627x; 1.1449x over previous
#include <cuda_runtime.h>
#include <cuda_fp16.h>
#include <cstdint>

// ============================================================================
// out[i] = W2 @ relu(W1 @ x_i + b1) + b2  for i >= 4
// rows 0..3 all equal W2 @ relu(W1 @ mean(x_0..3) + b1) + b2
//
// mma.sync m16n8k16 fp16/fp32-accum. A = rn-fp16 single; W1 split hi+lo
// (2 passes); W2 single pass (hi only). X loaded as float4 with a k-slot
// permutation matched by W1's smem layout (fewer L1 wavefronts).
// ============================================================================

#define TM       512      // rows per CTA
#define THREADS  512      // 16 warps x 32 rows

// smem layout (bytes)
#define S_W1     272
#define S_W2     144
#define OFF_W1HI 0
#define OFF_W1LO 17408
#define OFF_W2HI 34816
#define WBYTES   44032

__device__ __forceinline__ uint32_t smem_u32(const void* p) {
    uint32_t a;
    asm("{ .reg .u64 t; cvta.to.shared.u64 t, %1; cvt.u32.u64 %0, t; }"
        : "=r"(a) : "l"(p));
    return a;
}

// pack two fp32 -> f16x2 (x0 in low half)
__device__ __forceinline__ uint32_t pack_f16(float x0, float x1) {
    uint32_t r;
    asm("cvt.rn.f16x2.f32 %0, %1, %2;" : "=r"(r) : "f"(x1), "f"(x0));
    return r;
}

__device__ __forceinline__ void ldsm4(uint32_t* r, uint32_t addr) {
    asm volatile("ldmatrix.sync.aligned.m8n8.x4.shared.b16 {%0,%1,%2,%3}, [%4];"
                 : "=r"(r[0]), "=r"(r[1]), "=r"(r[2]), "=r"(r[3])
                 : "r"(addr));
}

__device__ __forceinline__ void mma_f16(float* d, const uint32_t* a,
                                        uint32_t b0, uint32_t b1) {
    asm volatile(
        "mma.sync.aligned.m16n8k16.row.col.f32.f16.f16.f32 "
        "{%0,%1,%2,%3}, {%4,%5,%6,%7}, {%8,%9}, {%0,%1,%2,%3};"
        : "+f"(d[0]), "+f"(d[1]), "+f"(d[2]), "+f"(d[3])
        : "r"(a[0]), "r"(a[1]), "r"(a[2]), "r"(a[3]), "r"(b0), "r"(b1));
}

__global__ void __launch_bounds__(THREADS, 1)
mlp_main(const float* __restrict__ audio, const float* __restrict__ video,
         const float* __restrict__ x1,    const float* __restrict__ x2,
         const float* __restrict__ W1,    const float* __restrict__ b1,
         const float* __restrict__ W2,    const float* __restrict__ b2,
         float* __restrict__ out, long nrows) {
    extern __shared__ char smem[];
    const uint32_t sb = smem_u32(smem);
    const int tid = threadIdx.x;

    // ---- stage 0: weights -> fp16 smem ----
    // W1: hi + lo (residual), stored k-PERMUTED so that float4 X loads map
    //     directly onto mma A-fragment slots:
    //       physical k = 16*blk + 4*q + {0,1}  ->  frag slot 16*blk + 2q + {0,1}
    //       physical k = 16*blk + 4*q + {2,3}  ->  frag slot 16*blk + 2q+8 + {0,1}
    // W2: hi only, standard layout.
    {
        const float4* W1f4 = (const float4*)W1;   // 2048 float4
        const float4* W2f4 = (const float4*)W2;   // 1024 float4
#pragma unroll
        for (int it = 0; it < 6; it++) {          // 3072 float4 total
            int i = tid + it * THREADS;
            if (i < 2048) {
                float4 v = W1f4[i];
                int n = i >> 5, k4 = i & 31;
                int kb = (k4 & ~3) * 4;           // 16-block base (elements)
                int q  = k4 & 3;
                int f0 = kb + 2 * q;              // slot for (v.x, v.y)
                int f1 = kb + 2 * q + 8;          // slot for (v.z, v.w)
                uint32_t h0 = pack_f16(v.x, v.y);
                uint32_t h1 = pack_f16(v.z, v.w);
                __half2 a0 = *(__half2*)&h0;
                __half2 a1 = *(__half2*)&h1;
                uint32_t l0 = pack_f16(v.x - __low2float(a0), v.y - __high2float(a0));
                uint32_t l1 = pack_f16(v.z - __low2float(a1), v.w - __high2float(a1));
                *(uint32_t*)(smem + OFF_W1HI + n * S_W1 + f0 * 2) = h0;
                *(uint32_t*)(smem + OFF_W1HI + n * S_W1 + f1 * 2) = h1;
                *(uint32_t*)(smem + OFF_W1LO + n * S_W1 + f0 * 2) = l0;
                *(uint32_t*)(smem + OFF_W1LO + n * S_W1 + f1 * 2) = l1;
            } else {
                int j = i - 2048;
                float4 v = W2f4[j];
                int n = j >> 4, k4 = j & 15;
                uint2 hp;
                hp.x = pack_f16(v.x, v.y);
                hp.y = pack_f16(v.z, v.w);
                *(uint2*)(smem + OFF_W2HI + n * S_W2 + k4 * 8) = hp;   // FIXED: *8
            }
        }
    }
    __syncthreads();

    const int wid  = tid >> 5;
    const int lane = tid & 31;
    const int r = lane >> 2;      // fragment row 0..7
    const int q = lane & 3;       // fragment col quad

    const long row0 = (long)blockIdx.x * TM;
    const long orow = row0 + wid * 32 + r;     // strip0 rows: orow, orow+8
    const bool full = (row0 + TM) <= nrows;    // strip1 rows: +16, +24
    long lr[4];
#pragma unroll
    for (int s = 0; s < 4; s++) {
        long rr = orow + s * 8;
        if (!full) { long mx = nrows - 1; rr = rr < mx ? rr : mx; }
        lr[s] = rr;
    }

    // per-lane ldmatrix base offsets
    const int rowp = ((lane >> 4) & 1) * 8 + (lane & 7);
    const int kadd = ((lane >> 3) & 1) * 16;
    const uint32_t aW1hi = sb + OFF_W1HI + rowp * S_W1 + kadd;
    const uint32_t aW1lo = sb + OFF_W1LO + rowp * S_W1 + kadd;
    const uint32_t aW2hi = sb + OFF_W2HI + rowp * S_W2 + kadd;

    const float* mods[4] = {audio, video, x1, x2};

    // ---- GEMM1: two 16-row strips share B fragments ----
    float acc0[8][4], acc1[8][4];
#pragma unroll
    for (int j = 0; j < 8; j++)
#pragma unroll
        for (int i = 0; i < 4; i++) { acc0[j][i] = 0.f; acc1[j][i] = 0.f; }

    // one float4 per row per k-tile: physical k cols q*4..q*4+3
    float4 p[4];
    {
        const float* pm = mods[0];
        const int co = q * 4;
#pragma unroll
        for (int s = 0; s < 4; s++)
            p[s] = *(const float4*)(pm + lr[s] * 32 + co);
    }

#pragma unroll
    for (int kt = 0; kt < 8; kt++) {
        float4 nx[4];
        if (kt < 7) {
            const float* pm = mods[(kt + 1) >> 1];
            const int co = ((kt + 1) & 1) * 16 + q * 4;
#pragma unroll
            for (int s = 0; s < 4; s++)
                nx[s] = *(const float4*)(pm + lr[s] * 32 + co);
        }

        // A frags under the k-permutation:
        //   reg0 = (row r,   k-lo) = (v.x, v.y); reg1 = (row r+8, k-lo)
        //   reg2 = (row r,   k-hi) = (v.z, v.w); reg3 = (row r+8, k-hi)
        uint32_t ah0[4], ah1[4];
        ah0[0] = pack_f16(p[0].x, p[0].y);
        ah0[1] = pack_f16(p[1].x, p[1].y);
        ah0[2] = pack_f16(p[0].z, p[0].w);
        ah0[3] = pack_f16(p[1].z, p[1].w);
        ah1[0] = pack_f16(p[2].x, p[2].y);
        ah1[1] = pack_f16(p[3].x, p[3].y);
        ah1[2] = pack_f16(p[2].z, p[2].w);
        ah1[3] = pack_f16(p[3].z, p[3].w);

#pragma unroll
        for (int j = 0; j < 4; j++) {
            uint32_t bh[4], bl[4];
            ldsm4(bh, aW1hi + j * (16 * S_W1) + kt * 32);
            ldsm4(bl, aW1lo + j * (16 * S_W1) + kt * 32);
            mma_f16(acc0[2*j],   ah0, bh[0], bh[1]);
            mma_f16(acc0[2*j],   ah0, bl[0], bl[1]);
            mma_f16(acc0[2*j+1], ah0, bh[2], bh[3]);
            mma_f16(acc0[2*j+1], ah0, bl[2], bl[3]);
            mma_f16(acc1[2*j],   ah1, bh[0], bh[1]);
            mma_f16(acc1[2*j],   ah1, bl[0], bl[1]);
            mma_f16(acc1[2*j+1], ah1, bh[2], bh[3]);
            mma_f16(acc1[2*j+1], ah1, bl[2], bl[3]);
        }
#pragma unroll
        for (int s = 0; s < 4; s++) p[s] = nx[s];
    }

    // ---- epilogue 1: H = relu(acc + b1) -> fp16 frags (both strips) ----
    uint32_t hr0[8], hr08[8], hr1[8], hr18[8];
#pragma unroll
    for (int j = 0; j < 8; j++) {
        float2 bv = *(const float2*)(b1 + j * 8 + q * 2);
        hr0[j]  = pack_f16(fmaxf(acc0[j][0] + bv.x, 0.f),
                           fmaxf(acc0[j][1] + bv.y, 0.f));
        hr08[j] = pack_f16(fmaxf(acc0[j][2] + bv.x, 0.f),
                           fmaxf(acc0[j][3] + bv.y, 0.f));
        hr1[j]  = pack_f16(fmaxf(acc1[j][0] + bv.x, 0.f),
                           fmaxf(acc1[j][1] + bv.y, 0.f));
        hr18[j] = pack_f16(fmaxf(acc1[j][2] + bv.x, 0.f),
                           fmaxf(acc1[j][3] + bv.y, 0.f));
    }

    // ---- GEMM2 (single pass, W2 hi) + store, j-outer; frags shared by strips
    const bool s0a = full || (orow      < nrows);
    const bool s0b = full || (orow + 8  < nrows);
    const bool s1a = full || (orow + 16 < nrows);
    const bool s1b = full || (orow + 24 < nrows);

#pragma unroll
    for (int j = 0; j < 4; j++) {
        float c0[2][4], c1[2][4];   // [ntile 2j / 2j+1][frag]
#pragma unroll
        for (int u = 0; u < 2; u++)
#pragma unroll
            for (int i = 0; i < 4; i++) { c0[u][i] = 0.f; c1[u][i] = 0.f; }

#pragma unroll
        for (int t = 0; t < 4; t++) {
            uint32_t bh[4];
            ldsm4(bh, aW2hi + j * (16 * S_W2) + t * 32);
            uint32_t a0[4] = {hr0[2*t], hr08[2*t], hr0[2*t+1], hr08[2*t+1]};
            uint32_t a1[4] = {hr1[2*t], hr18[2*t], hr1[2*t+1], hr18[2*t+1]};
            mma_f16(c0[0], a0, bh[0], bh[1]);
            mma_f16(c0[1], a0, bh[2], bh[3]);
            mma_f16(c1[0], a1, bh[0], bh[1]);
            mma_f16(c1[1], a1, bh[2], bh[3]);
        }

#pragma unroll
        for (int u = 0; u < 2; u++) {
            int col = (2*j + u) * 8 + q * 2;
            float2 bv = *(const float2*)(b2 + col);
            if (s0a) *(float2*)(out + orow * 64 + col) =
                make_float2(c0[u][0] + bv.x, c0[u][1] + bv.y);
            if (s0b) *(float2*)(out + (orow + 8) * 64 + col) =
                make_float2(c0[u][2] + bv.x, c0[u][3] + bv.y);
            if (s1a) *(float2*)(out + (orow + 16) * 64 + col) =
                make_float2(c1[u][0] + bv.x, c1[u][1] + bv.y);
            if (s1b) *(float2*)(out + (orow + 24) * 64 + col) =
                make_float2(c1[u][2] + bv.x, c1[u][3] + bv.y);
        }
    }

    // ---- block 0: exact fp32 fixup for graph rows 0..3 ----
    if (blockIdx.x == 0) {
        __syncthreads();
        float* xbar = (float*)smem;      // weights in smem are dead now
        float* h    = xbar + 128;
        const int t = tid;
        if (t < 128) {
            const float* pm = mods[t >> 5];
            int c = t & 31;
            xbar[t] = 0.25f * (pm[c] + pm[32 + c] + pm[64 + c] + pm[96 + c]);
        }
        __syncthreads();
        if (t < 64) {
            float s = 0.f;
            const float* wr = &W1[t * 128];
#pragma unroll 8
            for (int k = 0; k < 128; k++) s = fmaf(wr[k], xbar[k], s);
            h[t] = fmaxf(s + b1[t], 0.f);
        }
        __syncthreads();
        if (t < 64) {
            float s = 0.f;
            const float* wr = &W2[t * 64];
#pragma unroll 8
            for (int j = 0; j < 64; j++) s = fmaf(wr[j], h[j], s);
            float v = s + b2[t];
            out[0 * 64 + t] = v;
            out[1 * 64 + t] = v;
            out[2 * 64 + t] = v;
            out[3 * 64 + t] = v;
        }
    }
}

extern "C" void kernel_launch(void* const* d_in, const int* in_sizes, int n_in,
                              void* d_out, int out_size) {
    const float* audio = (const float*)d_in[0];
    const float* video = (const float*)d_in[1];
    const float* x1    = (const float*)d_in[2];
    const float* x2    = (const float*)d_in[3];
    const float* W1    = (const float*)d_in[4];
    const float* b1    = (const float*)d_in[5];
    const float* W2    = (const float*)d_in[6];
    const float* b2    = (const float*)d_in[7];
    float* out = (float*)d_out;

    long nrows = (long)(in_sizes[0] / 32);
    int grid = (int)((nrows + TM - 1) / TM);

    cudaFuncSetAttribute(mlp_main, cudaFuncAttributeMaxDynamicSharedMemorySize,
                         WBYTES);

    mlp_main<<<grid, THREADS, WBYTES>>>(audio, video, x1, x2, W1, b1, W2, b2,
                                        out, nrows);
}

// round 9
// speedup vs baseline: 1.3750x; 1.0091x over previous
#include <cuda_runtime.h>
#include <cuda_fp16.h>
#include <cstdint>

// ============================================================================
// out[i] = W2 @ relu(W1 @ x_i + b1) + b2  for i >= 4
// rows 0..3 all equal W2 @ relu(W1 @ mean(x_0..3) + b1) + b2
//
// mma.sync m16n8k16 fp16/fp32-accum. A = rn-fp16; W1 split hi+lo (2 passes);
// W2 single pass. X streamed via 5-stage cp.async pipeline (write-set ==
// read-set per thread => wait_group-only sync, no barriers in mainloop).
// ============================================================================

#define TM       512      // rows per CTA
#define THREADS  512      // 16 warps x 32 rows

// smem layout (bytes)
#define S_W1     272
#define S_W2     144
#define OFF_W1HI 0
#define OFF_W1LO 17408
#define OFF_W2HI 34816
#define WBYTES   44032
#define XOFF     44032
#define XSTAGE   32768    // 512 rows x 64B per k-tile
#define NSTAGE   5
#define SMEM_TOTAL (XOFF + NSTAGE * XSTAGE)   // 207872

__device__ __forceinline__ uint32_t smem_u32(const void* p) {
    uint32_t a;
    asm("{ .reg .u64 t; cvta.to.shared.u64 t, %1; cvt.u32.u64 %0, t; }"
        : "=r"(a) : "l"(p));
    return a;
}

__device__ __forceinline__ uint32_t pack_f16(float x0, float x1) {
    uint32_t r;
    asm("cvt.rn.f16x2.f32 %0, %1, %2;" : "=r"(r) : "f"(x1), "f"(x0));
    return r;
}

__device__ __forceinline__ void ldsm4(uint32_t* r, uint32_t addr) {
    asm volatile("ldmatrix.sync.aligned.m8n8.x4.shared.b16 {%0,%1,%2,%3}, [%4];"
                 : "=r"(r[0]), "=r"(r[1]), "=r"(r[2]), "=r"(r[3])
                 : "r"(addr));
}

__device__ __forceinline__ void mma_f16(float* d, const uint32_t* a,
                                        uint32_t b0, uint32_t b1) {
    asm volatile(
        "mma.sync.aligned.m16n8k16.row.col.f32.f16.f16.f32 "
        "{%0,%1,%2,%3}, {%4,%5,%6,%7}, {%8,%9}, {%0,%1,%2,%3};"
        : "+f"(d[0]), "+f"(d[1]), "+f"(d[2]), "+f"(d[3])
        : "r"(a[0]), "r"(a[1]), "r"(a[2]), "r"(a[3]), "r"(b0), "r"(b1));
}

__device__ __forceinline__ void cp16(uint32_t dst, const float* src) {
    asm volatile("cp.async.cg.shared.global [%0], [%1], 16;"
                 :: "r"(dst), "l"(__cvta_generic_to_global(src)) : "memory");
}
__device__ __forceinline__ void cp_commit() {
    asm volatile("cp.async.commit_group;" ::: "memory");
}
__device__ __forceinline__ void cp_wait_n(int n) {
    if (n == 0)      asm volatile("cp.async.wait_group 0;" ::: "memory");
    else if (n == 1) asm volatile("cp.async.wait_group 1;" ::: "memory");
    else if (n == 2) asm volatile("cp.async.wait_group 2;" ::: "memory");
    else             asm volatile("cp.async.wait_group 3;" ::: "memory");
}
__device__ __forceinline__ uint4 lds128(uint32_t a) {
    uint4 v;
    asm volatile("ld.shared.v4.u32 {%0,%1,%2,%3}, [%4];"
                 : "=r"(v.x), "=r"(v.y), "=r"(v.z), "=r"(v.w) : "r"(a));
    return v;
}

__global__ void __launch_bounds__(THREADS, 1)
mlp_main(const float* __restrict__ audio, const float* __restrict__ video,
         const float* __restrict__ x1,    const float* __restrict__ x2,
         const float* __restrict__ W1,    const float* __restrict__ b1,
         const float* __restrict__ W2,    const float* __restrict__ b2,
         float* __restrict__ out, long nrows) {
    extern __shared__ char smem[];
    const uint32_t sb = smem_u32(smem);
    const int tid = threadIdx.x;
    const int wid  = tid >> 5;
    const int lane = tid & 31;
    const int r = lane >> 2;      // fragment row 0..7
    const int q = lane & 3;       // fragment col quad

    const long row0 = (long)blockIdx.x * TM;
    const long orow = row0 + wid * 32 + r;
    const bool full = (row0 + TM) <= nrows;
    long lr[4];
#pragma unroll
    for (int s = 0; s < 4; s++) {
        long rr = orow + s * 8;
        if (!full) { long mx = nrows - 1; rr = rr < mx ? rr : mx; }
        lr[s] = rr;
    }

    const float* mods[4] = {audio, video, x1, x2};

    // per-thread X smem base: its own 4 chunks (rows r+8s, bytes q*16)
    const uint32_t xbase = sb + XOFF + (wid * 32 + r) * 64 + q * 16;

    // ---- X pipeline prologue: issue stages 0..3 ----
#pragma unroll
    for (int st = 0; st < 4; st++) {
        const float* pm = mods[st >> 1];
        const int co = (st & 1) * 16 + q * 4;
        uint32_t dst = xbase + st * XSTAGE;
#pragma unroll
        for (int s = 0; s < 4; s++)
            cp16(dst + s * 512, pm + lr[s] * 32 + co);
        cp_commit();
    }

    // ---- stage 0: weights -> fp16 smem (k-permuted W1 hi/lo, W2 hi) ----
    {
        const float4* W1f4 = (const float4*)W1;   // 2048 float4
        const float4* W2f4 = (const float4*)W2;   // 1024 float4
#pragma unroll
        for (int it = 0; it < 6; it++) {          // 3072 float4 total
            int i = tid + it * THREADS;
            if (i < 2048) {
                float4 v = W1f4[i];
                int n = i >> 5, k4 = i & 31;
                int kb = (k4 & ~3) * 4;
                int qq = k4 & 3;
                int f0 = kb + 2 * qq;
                int f1 = kb + 2 * qq + 8;
                uint32_t h0 = pack_f16(v.x, v.y);
                uint32_t h1 = pack_f16(v.z, v.w);
                __half2 a0 = *(__half2*)&h0;
                __half2 a1 = *(__half2*)&h1;
                uint32_t l0 = pack_f16(v.x - __low2float(a0), v.y - __high2float(a0));
                uint32_t l1 = pack_f16(v.z - __low2float(a1), v.w - __high2float(a1));
                *(uint32_t*)(smem + OFF_W1HI + n * S_W1 + f0 * 2) = h0;
                *(uint32_t*)(smem + OFF_W1HI + n * S_W1 + f1 * 2) = h1;
                *(uint32_t*)(smem + OFF_W1LO + n * S_W1 + f0 * 2) = l0;
                *(uint32_t*)(smem + OFF_W1LO + n * S_W1 + f1 * 2) = l1;
            } else {
                int j = i - 2048;
                float4 v = W2f4[j];
                int n = j >> 4, k4 = j & 15;
                uint2 hp;
                hp.x = pack_f16(v.x, v.y);
                hp.y = pack_f16(v.z, v.w);
                *(uint2*)(smem + OFF_W2HI + n * S_W2 + k4 * 8) = hp;
            }
        }
    }
    __syncthreads();

    // per-lane ldmatrix base offsets
    const int rowp = ((lane >> 4) & 1) * 8 + (lane & 7);
    const int kadd = ((lane >> 3) & 1) * 16;
    const uint32_t aW1hi = sb + OFF_W1HI + rowp * S_W1 + kadd;
    const uint32_t aW1lo = sb + OFF_W1LO + rowp * S_W1 + kadd;
    const uint32_t aW2hi = sb + OFF_W2HI + rowp * S_W2 + kadd;

    // ---- GEMM1: two 16-row strips share B fragments ----
    float acc0[8][4], acc1[8][4];
#pragma unroll
    for (int j = 0; j < 8; j++)
#pragma unroll
        for (int i = 0; i < 4; i++) { acc0[j][i] = 0.f; acc1[j][i] = 0.f; }

#pragma unroll
    for (int kt = 0; kt < 8; kt++) {
        // stage kt ready when <= min(3, 7-kt) groups outstanding
        cp_wait_n(kt < 4 ? 3 : 7 - kt);

        const uint32_t xsrc = xbase + (kt % NSTAGE) * XSTAGE;
        uint4 pv[4];
#pragma unroll
        for (int s = 0; s < 4; s++) pv[s] = lds128(xsrc + s * 512);

        // issue stage kt+4 (buffer (kt+4)%5 is free: only 5 stages live)
        if (kt + 4 < 8) {
            int st = kt + 4;
            const float* pm = mods[st >> 1];
            const int co = (st & 1) * 16 + q * 4;
            uint32_t dst = xbase + (st % NSTAGE) * XSTAGE;
#pragma unroll
            for (int s = 0; s < 4; s++)
                cp16(dst + s * 512, pm + lr[s] * 32 + co);
            cp_commit();
        }

        // A frags under the k-permutation (matches W1 smem layout):
        //   reg0=(r, k-lo)=(v.x,v.y); reg1=(r+8, k-lo); reg2=(r, k-hi)=(v.z,v.w)...
        uint32_t ah0[4], ah1[4];
        ah0[0] = pack_f16(__uint_as_float(pv[0].x), __uint_as_float(pv[0].y));
        ah0[1] = pack_f16(__uint_as_float(pv[1].x), __uint_as_float(pv[1].y));
        ah0[2] = pack_f16(__uint_as_float(pv[0].z), __uint_as_float(pv[0].w));
        ah0[3] = pack_f16(__uint_as_float(pv[1].z), __uint_as_float(pv[1].w));
        ah1[0] = pack_f16(__uint_as_float(pv[2].x), __uint_as_float(pv[2].y));
        ah1[1] = pack_f16(__uint_as_float(pv[3].x), __uint_as_float(pv[3].y));
        ah1[2] = pack_f16(__uint_as_float(pv[2].z), __uint_as_float(pv[2].w));
        ah1[3] = pack_f16(__uint_as_float(pv[3].z), __uint_as_float(pv[3].w));

#pragma unroll
        for (int j = 0; j < 4; j++) {
            uint32_t bh[4], bl[4];
            ldsm4(bh, aW1hi + j * (16 * S_W1) + kt * 32);
            ldsm4(bl, aW1lo + j * (16 * S_W1) + kt * 32);
            mma_f16(acc0[2*j],   ah0, bh[0], bh[1]);
            mma_f16(acc0[2*j],   ah0, bl[0], bl[1]);
            mma_f16(acc0[2*j+1], ah0, bh[2], bh[3]);
            mma_f16(acc0[2*j+1], ah0, bl[2], bl[3]);
            mma_f16(acc1[2*j],   ah1, bh[0], bh[1]);
            mma_f16(acc1[2*j],   ah1, bl[0], bl[1]);
            mma_f16(acc1[2*j+1], ah1, bh[2], bh[3]);
            mma_f16(acc1[2*j+1], ah1, bl[2], bl[3]);
        }
    }

    // ---- epilogue 1: H = relu(acc + b1) -> fp16 frags ----
    uint32_t hr0[8], hr08[8], hr1[8], hr18[8];
#pragma unroll
    for (int j = 0; j < 8; j++) {
        float2 bv = *(const float2*)(b1 + j * 8 + q * 2);
        hr0[j]  = pack_f16(fmaxf(acc0[j][0] + bv.x, 0.f),
                           fmaxf(acc0[j][1] + bv.y, 0.f));
        hr08[j] = pack_f16(fmaxf(acc0[j][2] + bv.x, 0.f),
                           fmaxf(acc0[j][3] + bv.y, 0.f));
        hr1[j]  = pack_f16(fmaxf(acc1[j][0] + bv.x, 0.f),
                           fmaxf(acc1[j][1] + bv.y, 0.f));
        hr18[j] = pack_f16(fmaxf(acc1[j][2] + bv.x, 0.f),
                           fmaxf(acc1[j][3] + bv.y, 0.f));
    }

    // ---- GEMM2 (single pass) + store, j-outer; frags shared by strips ----
    const bool s0a = full || (orow      < nrows);
    const bool s0b = full || (orow + 8  < nrows);
    const bool s1a = full || (orow + 16 < nrows);
    const bool s1b = full || (orow + 24 < nrows);

#pragma unroll
    for (int j = 0; j < 4; j++) {
        float c0[2][4], c1[2][4];
#pragma unroll
        for (int u = 0; u < 2; u++)
#pragma unroll
            for (int i = 0; i < 4; i++) { c0[u][i] = 0.f; c1[u][i] = 0.f; }

#pragma unroll
        for (int t = 0; t < 4; t++) {
            uint32_t bh[4];
            ldsm4(bh, aW2hi + j * (16 * S_W2) + t * 32);
            uint32_t a0[4] = {hr0[2*t], hr08[2*t], hr0[2*t+1], hr08[2*t+1]};
            uint32_t a1[4] = {hr1[2*t], hr18[2*t], hr1[2*t+1], hr18[2*t+1]};
            mma_f16(c0[0], a0, bh[0], bh[1]);
            mma_f16(c0[1], a0, bh[2], bh[3]);
            mma_f16(c1[0], a1, bh[0], bh[1]);
            mma_f16(c1[1], a1, bh[2], bh[3]);
        }

#pragma unroll
        for (int u = 0; u < 2; u++) {
            int col = (2*j + u) * 8 + q * 2;
            float2 bv = *(const float2*)(b2 + col);
            if (s0a) *(float2*)(out + orow * 64 + col) =
                make_float2(c0[u][0] + bv.x, c0[u][1] + bv.y);
            if (s0b) *(float2*)(out + (orow + 8) * 64 + col) =
                make_float2(c0[u][2] + bv.x, c0[u][3] + bv.y);
            if (s1a) *(float2*)(out + (orow + 16) * 64 + col) =
                make_float2(c1[u][0] + bv.x, c1[u][1] + bv.y);
            if (s1b) *(float2*)(out + (orow + 24) * 64 + col) =
                make_float2(c1[u][2] + bv.x, c1[u][3] + bv.y);
        }
    }

    // ---- block 0: exact fp32 fixup for graph rows 0..3 ----
    if (blockIdx.x == 0) {
        __syncthreads();
        float* xbar = (float*)smem;      // weights region is dead now
        float* h    = xbar + 128;
        const int t = tid;
        if (t < 128) {
            const float* pm = mods[t >> 5];
            int c = t & 31;
            xbar[t] = 0.25f * (pm[c] + pm[32 + c] + pm[64 + c] + pm[96 + c]);
        }
        __syncthreads();
        if (t < 64) {
            float s = 0.f;
            const float* wr = &W1[t * 128];
#pragma unroll 8
            for (int k = 0; k < 128; k++) s = fmaf(wr[k], xbar[k], s);
            h[t] = fmaxf(s + b1[t], 0.f);
        }
        __syncthreads();
        if (t < 64) {
            float s = 0.f;
            const float* wr = &W2[t * 64];
#pragma unroll 8
            for (int j = 0; j < 64; j++) s = fmaf(wr[j], h[j], s);
            float v = s + b2[t];
            out[0 * 64 + t] = v;
            out[1 * 64 + t] = v;
            out[2 * 64 + t] = v;
            out[3 * 64 + t] = v;
        }
    }
}

extern "C" void kernel_launch(void* const* d_in, const int* in_sizes, int n_in,
                              void* d_out, int out_size) {
    const float* audio = (const float*)d_in[0];
    const float* video = (const float*)d_in[1];
    const float* x1    = (const float*)d_in[2];
    const float* x2    = (const float*)d_in[3];
    const float* W1    = (const float*)d_in[4];
    const float* b1    = (const float*)d_in[5];
    const float* W2    = (const float*)d_in[6];
    const float* b2    = (const float*)d_in[7];
    float* out = (float*)d_out;

    long nrows = (long)(in_sizes[0] / 32);
    int grid = (int)((nrows + TM - 1) / TM);

    cudaFuncSetAttribute(mlp_main, cudaFuncAttributeMaxDynamicSharedMemorySize,
                         SMEM_TOTAL);

    mlp_main<<<grid, THREADS, SMEM_TOTAL>>>(audio, video, x1, x2, W1, b1, W2, b2,
                                            out, nrows);
}

// round 10
// speedup vs baseline: 1.5427x; 1.1219x over previous
#include <cuda_runtime.h>
#include <cuda_fp16.h>
#include <cstdint>

// ============================================================================
// out[i] = W2 @ relu(W1 @ x_i + b1) + b2  for i >= 4
// rows 0..3 all equal W2 @ relu(W1 @ mean(x_0..3) + b1) + b2
//
// mma.sync m16n8k16 fp16/fp32-accum, ALL single-pass (A, W1, W2 rn-fp16).
// Error budget: 3 independent fp16 rounding sources ~= 4.1e-4 rel (vs 1e-3).
// X streamed via 5-stage cp.async pipeline (per-thread write-set == read-set
// => wait_group-only sync, no barriers in mainloop).
// ============================================================================

#define TM       512      // rows per CTA
#define THREADS  512      // 16 warps x 32 rows

// smem layout (bytes)
#define S_W1     272
#define S_W2     144
#define OFF_W1HI 0
#define OFF_W2HI 17408
#define WBYTES   26624
#define XOFF     26624
#define XSTAGE   32768    // 512 rows x 64B per k-tile
#define NSTAGE   5
#define SMEM_TOTAL (XOFF + NSTAGE * XSTAGE)   // 190464

__device__ __forceinline__ uint32_t smem_u32(const void* p) {
    uint32_t a;
    asm("{ .reg .u64 t; cvta.to.shared.u64 t, %1; cvt.u32.u64 %0, t; }"
        : "=r"(a) : "l"(p));
    return a;
}

__device__ __forceinline__ uint32_t pack_f16(float x0, float x1) {
    uint32_t r;
    asm("cvt.rn.f16x2.f32 %0, %1, %2;" : "=r"(r) : "f"(x1), "f"(x0));
    return r;
}

__device__ __forceinline__ void ldsm4(uint32_t* r, uint32_t addr) {
    asm volatile("ldmatrix.sync.aligned.m8n8.x4.shared.b16 {%0,%1,%2,%3}, [%4];"
                 : "=r"(r[0]), "=r"(r[1]), "=r"(r[2]), "=r"(r[3])
                 : "r"(addr));
}

__device__ __forceinline__ void mma_f16(float* d, const uint32_t* a,
                                        uint32_t b0, uint32_t b1) {
    asm volatile(
        "mma.sync.aligned.m16n8k16.row.col.f32.f16.f16.f32 "
        "{%0,%1,%2,%3}, {%4,%5,%6,%7}, {%8,%9}, {%0,%1,%2,%3};"
        : "+f"(d[0]), "+f"(d[1]), "+f"(d[2]), "+f"(d[3])
        : "r"(a[0]), "r"(a[1]), "r"(a[2]), "r"(a[3]), "r"(b0), "r"(b1));
}

__device__ __forceinline__ void cp16(uint32_t dst, const float* src) {
    asm volatile("cp.async.cg.shared.global [%0], [%1], 16;"
                 :: "r"(dst), "l"(__cvta_generic_to_global(src)) : "memory");
}
__device__ __forceinline__ void cp_commit() {
    asm volatile("cp.async.commit_group;" ::: "memory");
}
__device__ __forceinline__ void cp_wait_n(int n) {
    if (n == 0)      asm volatile("cp.async.wait_group 0;" ::: "memory");
    else if (n == 1) asm volatile("cp.async.wait_group 1;" ::: "memory");
    else if (n == 2) asm volatile("cp.async.wait_group 2;" ::: "memory");
    else             asm volatile("cp.async.wait_group 3;" ::: "memory");
}
__device__ __forceinline__ uint4 lds128(uint32_t a) {
    uint4 v;
    asm volatile("ld.shared.v4.u32 {%0,%1,%2,%3}, [%4];"
                 : "=r"(v.x), "=r"(v.y), "=r"(v.z), "=r"(v.w) : "r"(a));
    return v;
}
// streaming store (evict-first): output has zero reuse
__device__ __forceinline__ void stcs2(float* p, float a, float b) {
    asm volatile("st.global.cs.v2.f32 [%0], {%1, %2};"
                 :: "l"(__cvta_generic_to_global(p)), "f"(a), "f"(b) : "memory");
}

__global__ void __launch_bounds__(THREADS, 1)
mlp_main(const float* __restrict__ audio, const float* __restrict__ video,
         const float* __restrict__ x1,    const float* __restrict__ x2,
         const float* __restrict__ W1,    const float* __restrict__ b1,
         const float* __restrict__ W2,    const float* __restrict__ b2,
         float* __restrict__ out, long nrows) {
    extern __shared__ char smem[];
    const uint32_t sb = smem_u32(smem);
    const int tid = threadIdx.x;
    const int wid  = tid >> 5;
    const int lane = tid & 31;
    const int r = lane >> 2;      // fragment row 0..7
    const int q = lane & 3;       // fragment col quad

    const long row0 = (long)blockIdx.x * TM;
    const long orow = row0 + wid * 32 + r;
    const bool full = (row0 + TM) <= nrows;
    long lr[4];
#pragma unroll
    for (int s = 0; s < 4; s++) {
        long rr = orow + s * 8;
        if (!full) { long mx = nrows - 1; rr = rr < mx ? rr : mx; }
        lr[s] = rr;
    }

    const float* mods[4] = {audio, video, x1, x2};

    // per-thread X smem base: its own 4 chunks (rows r+8s, bytes q*16)
    const uint32_t xbase = sb + XOFF + (wid * 32 + r) * 64 + q * 16;

    // ---- X pipeline prologue: issue stages 0..3 ----
#pragma unroll
    for (int st = 0; st < 4; st++) {
        const float* pm = mods[st >> 1];
        const int co = (st & 1) * 16 + q * 4;
        uint32_t dst = xbase + st * XSTAGE;
#pragma unroll
        for (int s = 0; s < 4; s++)
            cp16(dst + s * 512, pm + lr[s] * 32 + co);
        cp_commit();
    }

    // ---- stage 0: weights -> fp16 smem (k-permuted W1, standard W2) ----
    // W1 k-permutation matches float4 X loads onto A-fragment slots:
    //   physical k = 16*blk + 4*q + {0,1} -> slot 16*blk + 2q + {0,1}
    //   physical k = 16*blk + 4*q + {2,3} -> slot 16*blk + 2q+8 + {0,1}
    {
        const float4* W1f4 = (const float4*)W1;   // 2048 float4
        const float4* W2f4 = (const float4*)W2;   // 1024 float4
#pragma unroll
        for (int it = 0; it < 6; it++) {          // 3072 float4 total
            int i = tid + it * THREADS;
            if (i < 2048) {
                float4 v = W1f4[i];
                int n = i >> 5, k4 = i & 31;
                int kb = (k4 & ~3) * 4;
                int qq = k4 & 3;
                int f0 = kb + 2 * qq;
                int f1 = kb + 2 * qq + 8;
                *(uint32_t*)(smem + OFF_W1HI + n * S_W1 + f0 * 2) = pack_f16(v.x, v.y);
                *(uint32_t*)(smem + OFF_W1HI + n * S_W1 + f1 * 2) = pack_f16(v.z, v.w);
            } else {
                int j = i - 2048;
                float4 v = W2f4[j];
                int n = j >> 4, k4 = j & 15;
                uint2 hp;
                hp.x = pack_f16(v.x, v.y);
                hp.y = pack_f16(v.z, v.w);
                *(uint2*)(smem + OFF_W2HI + n * S_W2 + k4 * 8) = hp;
            }
        }
    }
    __syncthreads();

    // per-lane ldmatrix base offsets
    const int rowp = ((lane >> 4) & 1) * 8 + (lane & 7);
    const int kadd = ((lane >> 3) & 1) * 16;
    const uint32_t aW1hi = sb + OFF_W1HI + rowp * S_W1 + kadd;
    const uint32_t aW2hi = sb + OFF_W2HI + rowp * S_W2 + kadd;

    // ---- GEMM1: two 16-row strips share B fragments, single pass ----
    float acc0[8][4], acc1[8][4];
#pragma unroll
    for (int j = 0; j < 8; j++)
#pragma unroll
        for (int i = 0; i < 4; i++) { acc0[j][i] = 0.f; acc1[j][i] = 0.f; }

#pragma unroll
    for (int kt = 0; kt < 8; kt++) {
        cp_wait_n(kt < 4 ? 3 : 7 - kt);

        const uint32_t xsrc = xbase + (kt % NSTAGE) * XSTAGE;
        uint4 pv[4];
#pragma unroll
        for (int s = 0; s < 4; s++) pv[s] = lds128(xsrc + s * 512);

        if (kt + 4 < 8) {
            int st = kt + 4;
            const float* pm = mods[st >> 1];
            const int co = (st & 1) * 16 + q * 4;
            uint32_t dst = xbase + (st % NSTAGE) * XSTAGE;
#pragma unroll
            for (int s = 0; s < 4; s++)
                cp16(dst + s * 512, pm + lr[s] * 32 + co);
            cp_commit();
        }

        uint32_t ah0[4], ah1[4];
        ah0[0] = pack_f16(__uint_as_float(pv[0].x), __uint_as_float(pv[0].y));
        ah0[1] = pack_f16(__uint_as_float(pv[1].x), __uint_as_float(pv[1].y));
        ah0[2] = pack_f16(__uint_as_float(pv[0].z), __uint_as_float(pv[0].w));
        ah0[3] = pack_f16(__uint_as_float(pv[1].z), __uint_as_float(pv[1].w));
        ah1[0] = pack_f16(__uint_as_float(pv[2].x), __uint_as_float(pv[2].y));
        ah1[1] = pack_f16(__uint_as_float(pv[3].x), __uint_as_float(pv[3].y));
        ah1[2] = pack_f16(__uint_as_float(pv[2].z), __uint_as_float(pv[2].w));
        ah1[3] = pack_f16(__uint_as_float(pv[3].z), __uint_as_float(pv[3].w));

#pragma unroll
        for (int j = 0; j < 4; j++) {
            uint32_t bh[4];
            ldsm4(bh, aW1hi + j * (16 * S_W1) + kt * 32);
            mma_f16(acc0[2*j],   ah0, bh[0], bh[1]);
            mma_f16(acc0[2*j+1], ah0, bh[2], bh[3]);
            mma_f16(acc1[2*j],   ah1, bh[0], bh[1]);
            mma_f16(acc1[2*j+1], ah1, bh[2], bh[3]);
        }
    }

    // ---- epilogue 1: H = relu(acc + b1) -> fp16 frags ----
    uint32_t hr0[8], hr08[8], hr1[8], hr18[8];
#pragma unroll
    for (int j = 0; j < 8; j++) {
        float2 bv = *(const float2*)(b1 + j * 8 + q * 2);
        hr0[j]  = pack_f16(fmaxf(acc0[j][0] + bv.x, 0.f),
                           fmaxf(acc0[j][1] + bv.y, 0.f));
        hr08[j] = pack_f16(fmaxf(acc0[j][2] + bv.x, 0.f),
                           fmaxf(acc0[j][3] + bv.y, 0.f));
        hr1[j]  = pack_f16(fmaxf(acc1[j][0] + bv.x, 0.f),
                           fmaxf(acc1[j][1] + bv.y, 0.f));
        hr18[j] = pack_f16(fmaxf(acc1[j][2] + bv.x, 0.f),
                           fmaxf(acc1[j][3] + bv.y, 0.f));
    }

    // ---- GEMM2 (single pass) + store, j-outer; frags shared by strips ----
    const bool s0a = full || (orow      < nrows);
    const bool s0b = full || (orow + 8  < nrows);
    const bool s1a = full || (orow + 16 < nrows);
    const bool s1b = full || (orow + 24 < nrows);

#pragma unroll
    for (int j = 0; j < 4; j++) {
        float c0[2][4], c1[2][4];
#pragma unroll
        for (int u = 0; u < 2; u++)
#pragma unroll
            for (int i = 0; i < 4; i++) { c0[u][i] = 0.f; c1[u][i] = 0.f; }

#pragma unroll
        for (int t = 0; t < 4; t++) {
            uint32_t bh[4];
            ldsm4(bh, aW2hi + j * (16 * S_W2) + t * 32);
            uint32_t a0[4] = {hr0[2*t], hr08[2*t], hr0[2*t+1], hr08[2*t+1]};
            uint32_t a1[4] = {hr1[2*t], hr18[2*t], hr1[2*t+1], hr18[2*t+1]};
            mma_f16(c0[0], a0, bh[0], bh[1]);
            mma_f16(c0[1], a0, bh[2], bh[3]);
            mma_f16(c1[0], a1, bh[0], bh[1]);
            mma_f16(c1[1], a1, bh[2], bh[3]);
        }

#pragma unroll
        for (int u = 0; u < 2; u++) {
            int col = (2*j + u) * 8 + q * 2;
            float2 bv = *(const float2*)(b2 + col);
            if (s0a) stcs2(out + orow * 64 + col,
                           c0[u][0] + bv.x, c0[u][1] + bv.y);
            if (s0b) stcs2(out + (orow + 8) * 64 + col,
                           c0[u][2] + bv.x, c0[u][3] + bv.y);
            if (s1a) stcs2(out + (orow + 16) * 64 + col,
                           c1[u][0] + bv.x, c1[u][1] + bv.y);
            if (s1b) stcs2(out + (orow + 24) * 64 + col,
                           c1[u][2] + bv.x, c1[u][3] + bv.y);
        }
    }

    // ---- block 0: exact fp32 fixup for graph rows 0..3 ----
    if (blockIdx.x == 0) {
        __syncthreads();
        float* xbar = (float*)smem;      // weights region is dead now
        float* h    = xbar + 128;
        const int t = tid;
        if (t < 128) {
            const float* pm = mods[t >> 5];
            int c = t & 31;
            xbar[t] = 0.25f * (pm[c] + pm[32 + c] + pm[64 + c] + pm[96 + c]);
        }
        __syncthreads();
        if (t < 64) {
            float s = 0.f;
            const float* wr = &W1[t * 128];
#pragma unroll 8
            for (int k = 0; k < 128; k++) s = fmaf(wr[k], xbar[k], s);
            h[t] = fmaxf(s + b1[t], 0.f);
        }
        __syncthreads();
        if (t < 64) {
            float s = 0.f;
            const float* wr = &W2[t * 64];
#pragma unroll 8
            for (int j = 0; j < 64; j++) s = fmaf(wr[j], h[j], s);
            float v = s + b2[t];
            out[0 * 64 + t] = v;
            out[1 * 64 + t] = v;
            out[2 * 64 + t] = v;
            out[3 * 64 + t] = v;
        }
    }
}

extern "C" void kernel_launch(void* const* d_in, const int* in_sizes, int n_in,
                              void* d_out, int out_size) {
    const float* audio = (const float*)d_in[0];
    const float* video = (const float*)d_in[1];
    const float* x1    = (const float*)d_in[2];
    const float* x2    = (const float*)d_in[3];
    const float* W1    = (const float*)d_in[4];
    const float* b1    = (const float*)d_in[5];
    const float* W2    = (const float*)d_in[6];
    const float* b2    = (const float*)d_in[7];
    float* out = (float*)d_out;

    long nrows = (long)(in_sizes[0] / 32);
    int grid = (int)((nrows + TM - 1) / TM);

    cudaFuncSetAttribute(mlp_main, cudaFuncAttributeMaxDynamicSharedMemorySize,
                         SMEM_TOTAL);

    mlp_main<<<grid, THREADS, SMEM_TOTAL>>>(audio, video, x1, x2, W1, b1, W2, b2,
                                            out, nrows);
}

// round 11
// speedup vs baseline: 1.7143x; 1.1112x over previous
#include <cuda_runtime.h>
#include <cuda_fp16.h>
#include <cstdint>

// ============================================================================
// out[i] = W2 @ relu(W1 @ x_i + b1) + b2  for i >= 4
// rows 0..3 all equal W2 @ relu(W1 @ mean(x_0..3) + b1) + b2
//
// Persistent-CTA fused MLP. mma.sync m16n8k16 fp16/fp32-accum, single pass.
// X streamed via 5-stage cp.async pipeline that runs CONTINUOUSLY across
// tiles (epilogue overlapped with next tile's loads). Weights staged once.
// ============================================================================

#define TM       512      // rows per tile
#define THREADS  512      // 16 warps x 32 rows

// smem layout (bytes)
#define S_W1     272
#define S_W2     144
#define OFF_W1HI 0
#define OFF_W2HI 17408
#define OFF_BIAS 26624    // b1[64] f32, b2[64] f32
#define XOFF     27136
#define XSTAGE   32768    // 512 rows x 64B per k-tile stage
#define NSTAGE   5
#define SMEM_TOTAL (XOFF + NSTAGE * XSTAGE)   // 190976

__device__ __forceinline__ uint32_t smem_u32(const void* p) {
    uint32_t a;
    asm("{ .reg .u64 t; cvta.to.shared.u64 t, %1; cvt.u32.u64 %0, t; }"
        : "=r"(a) : "l"(p));
    return a;
}
__device__ __forceinline__ uint32_t pack_f16(float x0, float x1) {
    uint32_t r;
    asm("cvt.rn.f16x2.f32 %0, %1, %2;" : "=r"(r) : "f"(x1), "f"(x0));
    return r;
}
__device__ __forceinline__ void ldsm4(uint32_t* r, uint32_t addr) {
    asm volatile("ldmatrix.sync.aligned.m8n8.x4.shared.b16 {%0,%1,%2,%3}, [%4];"
                 : "=r"(r[0]), "=r"(r[1]), "=r"(r[2]), "=r"(r[3])
                 : "r"(addr));
}
__device__ __forceinline__ void mma_f16(float* d, const uint32_t* a,
                                        uint32_t b0, uint32_t b1) {
    asm volatile(
        "mma.sync.aligned.m16n8k16.row.col.f32.f16.f16.f32 "
        "{%0,%1,%2,%3}, {%4,%5,%6,%7}, {%8,%9}, {%0,%1,%2,%3};"
        : "+f"(d[0]), "+f"(d[1]), "+f"(d[2]), "+f"(d[3])
        : "r"(a[0]), "r"(a[1]), "r"(a[2]), "r"(a[3]), "r"(b0), "r"(b1));
}
__device__ __forceinline__ void cp16(uint32_t dst, const float* src) {
    asm volatile("cp.async.cg.shared.global [%0], [%1], 16;"
                 :: "r"(dst), "l"(__cvta_generic_to_global(src)) : "memory");
}
__device__ __forceinline__ void cp_commit() {
    asm volatile("cp.async.commit_group;" ::: "memory");
}
__device__ __forceinline__ void cp_wait3() {
    asm volatile("cp.async.wait_group 3;" ::: "memory");
}
__device__ __forceinline__ void cp_wait_all() {
    asm volatile("cp.async.wait_group 0;" ::: "memory");
}
__device__ __forceinline__ uint4 lds128(uint32_t a) {
    uint4 v;
    asm volatile("ld.shared.v4.u32 {%0,%1,%2,%3}, [%4];"
                 : "=r"(v.x), "=r"(v.y), "=r"(v.z), "=r"(v.w) : "r"(a));
    return v;
}
__device__ __forceinline__ void stcs2(float* p, float a, float b) {
    asm volatile("st.global.cs.v2.f32 [%0], {%1, %2};"
                 :: "l"(__cvta_generic_to_global(p)), "f"(a), "f"(b) : "memory");
}

__global__ void __launch_bounds__(THREADS, 1)
mlp_main(const float* __restrict__ audio, const float* __restrict__ video,
         const float* __restrict__ x1,    const float* __restrict__ x2,
         const float* __restrict__ W1,    const float* __restrict__ b1,
         const float* __restrict__ W2,    const float* __restrict__ b2,
         float* __restrict__ out, long nrows) {
    extern __shared__ char smem[];
    const uint32_t sb = smem_u32(smem);
    const int tid  = threadIdx.x;
    const int wid  = tid >> 5;
    const int lane = tid & 31;
    const int r = lane >> 2;      // fragment row 0..7
    const int q = lane & 3;       // fragment col quad

    const long bid     = blockIdx.x;
    const long gstride = gridDim.x;
    const long ntiles  = (nrows + TM - 1) / TM;

    const float* mods[4] = {audio, video, x1, x2};
    const uint32_t xbase = sb + XOFF + (wid * 32 + r) * 64 + q * 16;

    // issue one global stage s into buffer buf (empty commit if out of range)
    auto issue_stage = [&](long s, int buf) {
        long ti = bid + (s >> 3) * gstride;
        if (ti < ntiles) {
            int st = (int)(s & 7);
            long trow0 = ti * TM;
            const float* pm = mods[st >> 1];
            const int co = (st & 1) * 16 + q * 4;
            uint32_t dst = xbase + buf * XSTAGE;
#pragma unroll
            for (int ss = 0; ss < 4; ss++) {
                long rr = trow0 + wid * 32 + r + ss * 8;
                if (rr >= nrows) rr = nrows - 1;
                cp16(dst + ss * 512, pm + rr * 32 + co);
            }
        }
        cp_commit();
    };

    // ---- pipeline prologue: stages 0..3 ----
    issue_stage(0, 0);
    issue_stage(1, 1);
    issue_stage(2, 2);
    issue_stage(3, 3);

    // ---- weights -> fp16 smem (once per CTA; k-permuted W1, standard W2) ----
    {
        const float4* W1f4 = (const float4*)W1;   // 2048 float4
        const float4* W2f4 = (const float4*)W2;   // 1024 float4
#pragma unroll
        for (int it = 0; it < 6; it++) {
            int i = tid + it * THREADS;
            if (i < 2048) {
                float4 v = W1f4[i];
                int n = i >> 5, k4 = i & 31;
                int kb = (k4 & ~3) * 4;
                int qq = k4 & 3;
                int f0 = kb + 2 * qq;
                int f1 = kb + 2 * qq + 8;
                *(uint32_t*)(smem + OFF_W1HI + n * S_W1 + f0 * 2) = pack_f16(v.x, v.y);
                *(uint32_t*)(smem + OFF_W1HI + n * S_W1 + f1 * 2) = pack_f16(v.z, v.w);
            } else {
                int j = i - 2048;
                float4 v = W2f4[j];
                int n = j >> 4, k4 = j & 15;
                uint2 hp;
                hp.x = pack_f16(v.x, v.y);
                hp.y = pack_f16(v.z, v.w);
                *(uint2*)(smem + OFF_W2HI + n * S_W2 + k4 * 8) = hp;
            }
        }
        float* bs = (float*)(smem + OFF_BIAS);
        if (tid < 64)  bs[tid] = b1[tid];
        else if (tid < 128) bs[tid] = b2[tid - 64];   // b2 at +64 floats
    }
    __syncthreads();

    // per-lane ldmatrix base offsets
    const int rowp = ((lane >> 4) & 1) * 8 + (lane & 7);
    const int kadd = ((lane >> 3) & 1) * 16;
    const uint32_t aW1hi = sb + OFF_W1HI + rowp * S_W1 + kadd;
    const uint32_t aW2hi = sb + OFF_W2HI + rowp * S_W2 + kadd;
    const float* b1s = (const float*)(smem + OFF_BIAS);
    const float* b2s = b1s + 64;

    long s_next = 4;
    int bc = 0, bi = 4;

    // ================= persistent tile loop =================
    for (long tile = bid; tile < ntiles; tile += gstride) {
        float acc0[8][4], acc1[8][4];
#pragma unroll
        for (int j = 0; j < 8; j++)
#pragma unroll
            for (int i = 0; i < 4; i++) { acc0[j][i] = 0.f; acc1[j][i] = 0.f; }

#pragma unroll
        for (int kt = 0; kt < 8; kt++) {
            cp_wait3();
            const uint32_t xsrc = xbase + bc * XSTAGE;
            uint4 pv[4];
#pragma unroll
            for (int s = 0; s < 4; s++) pv[s] = lds128(xsrc + s * 512);

            issue_stage(s_next, bi);
            s_next++;
            bc = (bc == NSTAGE - 1) ? 0 : bc + 1;
            bi = (bi == NSTAGE - 1) ? 0 : bi + 1;

            uint32_t ah0[4], ah1[4];
            ah0[0] = pack_f16(__uint_as_float(pv[0].x), __uint_as_float(pv[0].y));
            ah0[1] = pack_f16(__uint_as_float(pv[1].x), __uint_as_float(pv[1].y));
            ah0[2] = pack_f16(__uint_as_float(pv[0].z), __uint_as_float(pv[0].w));
            ah0[3] = pack_f16(__uint_as_float(pv[1].z), __uint_as_float(pv[1].w));
            ah1[0] = pack_f16(__uint_as_float(pv[2].x), __uint_as_float(pv[2].y));
            ah1[1] = pack_f16(__uint_as_float(pv[3].x), __uint_as_float(pv[3].y));
            ah1[2] = pack_f16(__uint_as_float(pv[2].z), __uint_as_float(pv[2].w));
            ah1[3] = pack_f16(__uint_as_float(pv[3].z), __uint_as_float(pv[3].w));

#pragma unroll
            for (int j = 0; j < 4; j++) {
                uint32_t bh[4];
                ldsm4(bh, aW1hi + j * (16 * S_W1) + kt * 32);
                mma_f16(acc0[2*j],   ah0, bh[0], bh[1]);
                mma_f16(acc0[2*j+1], ah0, bh[2], bh[3]);
                mma_f16(acc1[2*j],   ah1, bh[0], bh[1]);
                mma_f16(acc1[2*j+1], ah1, bh[2], bh[3]);
            }
        }

        // ---- epilogue 1: H = relu(acc + b1) -> fp16 frags ----
        uint32_t hr0[8], hr08[8], hr1[8], hr18[8];
#pragma unroll
        for (int j = 0; j < 8; j++) {
            float2 bv = *(const float2*)(b1s + j * 8 + q * 2);
            hr0[j]  = pack_f16(fmaxf(acc0[j][0] + bv.x, 0.f),
                               fmaxf(acc0[j][1] + bv.y, 0.f));
            hr08[j] = pack_f16(fmaxf(acc0[j][2] + bv.x, 0.f),
                               fmaxf(acc0[j][3] + bv.y, 0.f));
            hr1[j]  = pack_f16(fmaxf(acc1[j][0] + bv.x, 0.f),
                               fmaxf(acc1[j][1] + bv.y, 0.f));
            hr18[j] = pack_f16(fmaxf(acc1[j][2] + bv.x, 0.f),
                               fmaxf(acc1[j][3] + bv.y, 0.f));
        }

        // ---- GEMM2 (single pass) + streaming stores ----
        const long orow = tile * TM + wid * 32 + r;
        const bool tfull = (tile * TM + TM) <= nrows;
        const bool s0a = tfull || (orow      < nrows);
        const bool s0b = tfull || (orow + 8  < nrows);
        const bool s1a = tfull || (orow + 16 < nrows);
        const bool s1b = tfull || (orow + 24 < nrows);

#pragma unroll
        for (int j = 0; j < 4; j++) {
            float c0[2][4], c1[2][4];
#pragma unroll
            for (int u = 0; u < 2; u++)
#pragma unroll
                for (int i = 0; i < 4; i++) { c0[u][i] = 0.f; c1[u][i] = 0.f; }

#pragma unroll
            for (int t = 0; t < 4; t++) {
                uint32_t bh[4];
                ldsm4(bh, aW2hi + j * (16 * S_W2) + t * 32);
                uint32_t a0[4] = {hr0[2*t], hr08[2*t], hr0[2*t+1], hr08[2*t+1]};
                uint32_t a1[4] = {hr1[2*t], hr18[2*t], hr1[2*t+1], hr18[2*t+1]};
                mma_f16(c0[0], a0, bh[0], bh[1]);
                mma_f16(c0[1], a0, bh[2], bh[3]);
                mma_f16(c1[0], a1, bh[0], bh[1]);
                mma_f16(c1[1], a1, bh[2], bh[3]);
            }

#pragma unroll
            for (int u = 0; u < 2; u++) {
                int col = (2*j + u) * 8 + q * 2;
                float2 bv = *(const float2*)(b2s + col);
                if (s0a) stcs2(out + orow * 64 + col,
                               c0[u][0] + bv.x, c0[u][1] + bv.y);
                if (s0b) stcs2(out + (orow + 8) * 64 + col,
                               c0[u][2] + bv.x, c0[u][3] + bv.y);
                if (s1a) stcs2(out + (orow + 16) * 64 + col,
                               c1[u][0] + bv.x, c1[u][1] + bv.y);
                if (s1b) stcs2(out + (orow + 24) * 64 + col,
                               c1[u][2] + bv.x, c1[u][3] + bv.y);
            }
        }
    }
    cp_wait_all();

    // ---- block 0: exact fp32 fixup for graph rows 0..3 ----
    if (blockIdx.x == 0) {
        __syncthreads();                 // all warps past their tile loop
        float* xbar = (float*)smem;      // weight region is dead now
        float* h    = xbar + 128;
        const int t = tid;
        if (t < 128) {
            const float* pm = mods[t >> 5];
            int c = t & 31;
            xbar[t] = 0.25f * (pm[c] + pm[32 + c] + pm[64 + c] + pm[96 + c]);
        }
        __syncthreads();
        if (t < 64) {
            float s = 0.f;
            const float* wr = &W1[t * 128];
#pragma unroll 8
            for (int k = 0; k < 128; k++) s = fmaf(wr[k], xbar[k], s);
            h[t] = fmaxf(s + b1[t], 0.f);
        }
        __syncthreads();
        if (t < 64) {
            float s = 0.f;
            const float* wr = &W2[t * 64];
#pragma unroll 8
            for (int j = 0; j < 64; j++) s = fmaf(wr[j], h[j], s);
            float v = s + b2[t];
            out[0 * 64 + t] = v;
            out[1 * 64 + t] = v;
            out[2 * 64 + t] = v;
            out[3 * 64 + t] = v;
        }
    }
}

extern "C" void kernel_launch(void* const* d_in, const int* in_sizes, int n_in,
                              void* d_out, int out_size) {
    const float* audio = (const float*)d_in[0];
    const float* video = (const float*)d_in[1];
    const float* x1    = (const float*)d_in[2];
    const float* x2    = (const float*)d_in[3];
    const float* W1    = (const float*)d_in[4];
    const float* b1    = (const float*)d_in[5];
    const float* W2    = (const float*)d_in[6];
    const float* b2    = (const float*)d_in[7];
    float* out = (float*)d_out;

    long nrows = (long)(in_sizes[0] / 32);
    long ntiles = (nrows + TM - 1) / TM;

    static int nsm = 0;
    if (nsm == 0) {
        cudaDeviceGetAttribute(&nsm, cudaDevAttrMultiProcessorCount, 0);
        if (nsm <= 0) nsm = 148;
        cudaFuncSetAttribute(mlp_main, cudaFuncAttributeMaxDynamicSharedMemorySize,
                             SMEM_TOTAL);
    }
    int grid = (int)(ntiles < (long)nsm ? ntiles : (long)nsm);

    mlp_main<<<grid, THREADS, SMEM_TOTAL>>>(audio, video, x1, x2, W1, b1, W2, b2,
                                            out, nrows);
}

// round 12
// speedup vs baseline: 1.7677x; 1.0312x over previous
#include <cuda_runtime.h>
#include <cuda_fp16.h>
#include <cstdint>

// ============================================================================
// out[i] = W2 @ relu(W1 @ x_i + b1) + b2  for i >= 4
// rows 0..3 all equal W2 @ relu(W1 @ mean(x_0..3) + b1) + b2
//
// Persistent-CTA fused MLP. mma.sync m16n8k16 fp16/fp32-accum, single pass.
// X streamed via 5-stage cp.async pipeline running continuously across tiles.
// Stage issuer is fully compile-time (templated on stage id) to keep ALU/AGU
// work out of the DRAM-bound mainloop.
// ============================================================================

#define TM       512      // rows per tile
#define THREADS  512      // 16 warps x 32 rows
#define TILEW    16384L   // TM * 32 words per tile per modality

// smem layout (bytes)
#define S_W1     272
#define S_W2     144
#define OFF_W1HI 0
#define OFF_W2HI 17408
#define OFF_BIAS 26624    // b1[64] f32, b2[64] f32
#define XOFF     27136
#define XSTAGE   32768    // 512 rows x 64B per k-tile stage
#define NSTAGE   5
#define SMEM_TOTAL (XOFF + NSTAGE * XSTAGE)   // 190976

__device__ __forceinline__ uint32_t smem_u32(const void* p) {
    uint32_t a;
    asm("{ .reg .u64 t; cvta.to.shared.u64 t, %1; cvt.u32.u64 %0, t; }"
        : "=r"(a) : "l"(p));
    return a;
}
__device__ __forceinline__ uint32_t pack_f16(float x0, float x1) {
    uint32_t r;
    asm("cvt.rn.f16x2.f32 %0, %1, %2;" : "=r"(r) : "f"(x1), "f"(x0));
    return r;
}
__device__ __forceinline__ void ldsm4(uint32_t* r, uint32_t addr) {
    asm volatile("ldmatrix.sync.aligned.m8n8.x4.shared.b16 {%0,%1,%2,%3}, [%4];"
                 : "=r"(r[0]), "=r"(r[1]), "=r"(r[2]), "=r"(r[3])
                 : "r"(addr));
}
__device__ __forceinline__ void mma_f16(float* d, const uint32_t* a,
                                        uint32_t b0, uint32_t b1) {
    asm volatile(
        "mma.sync.aligned.m16n8k16.row.col.f32.f16.f16.f32 "
        "{%0,%1,%2,%3}, {%4,%5,%6,%7}, {%8,%9}, {%0,%1,%2,%3};"
        : "+f"(d[0]), "+f"(d[1]), "+f"(d[2]), "+f"(d[3])
        : "r"(a[0]), "r"(a[1]), "r"(a[2]), "r"(a[3]), "r"(b0), "r"(b1));
}
__device__ __forceinline__ void cp16(uint32_t dst, const float* src) {
    asm volatile("cp.async.cg.shared.global [%0], [%1], 16;"
                 :: "r"(dst), "l"(__cvta_generic_to_global(src)) : "memory");
}
__device__ __forceinline__ void cp_commit() {
    asm volatile("cp.async.commit_group;" ::: "memory");
}
__device__ __forceinline__ void cp_wait3() {
    asm volatile("cp.async.wait_group 3;" ::: "memory");
}
__device__ __forceinline__ void cp_wait_all() {
    asm volatile("cp.async.wait_group 0;" ::: "memory");
}
__device__ __forceinline__ uint4 lds128(uint32_t a) {
    uint4 v;
    asm volatile("ld.shared.v4.u32 {%0,%1,%2,%3}, [%4];"
                 : "=r"(v.x), "=r"(v.y), "=r"(v.z), "=r"(v.w) : "r"(a));
    return v;
}
__device__ __forceinline__ void stcs2(float* p, float a, float b) {
    asm volatile("st.global.cs.v2.f32 [%0], {%1, %2};"
                 :: "l"(__cvta_generic_to_global(p)), "f"(a), "f"(b) : "memory");
}

// Compile-time stage issuer. ST in 0..7: modality ST>>1, k-half ST&1.
// offw = tile_base word offset; rowb = per-thread row base words; maxw = clamp.
template <int ST>
__device__ __forceinline__ void issue_ct(const float* const* mods, int q,
                                         long offw, int rowb, long maxw,
                                         bool ok, uint32_t dst) {
    if (ok) {
        const float* pm = mods[ST >> 1] + (ST & 1) * 16 + q * 4;
#pragma unroll
        for (int ss = 0; ss < 4; ss++) {
            long w = offw + rowb + ss * 256;
            if (w > maxw) w = maxw;
            cp16(dst + ss * 512, pm + w);
        }
    }
    cp_commit();
}

__global__ void __launch_bounds__(THREADS, 1)
mlp_main(const float* __restrict__ audio, const float* __restrict__ video,
         const float* __restrict__ x1,    const float* __restrict__ x2,
         const float* __restrict__ W1,    const float* __restrict__ b1,
         const float* __restrict__ W2,    const float* __restrict__ b2,
         float* __restrict__ out, long nrows) {
    extern __shared__ char smem[];
    const uint32_t sb = smem_u32(smem);
    const int tid  = threadIdx.x;
    const int wid  = tid >> 5;
    const int lane = tid & 31;
    const int r = lane >> 2;      // fragment row 0..7
    const int q = lane & 3;       // fragment col quad

    const long bid     = blockIdx.x;
    const long gstride = gridDim.x;
    const long ntiles  = (nrows + TM - 1) / TM;
    const long maxw    = (nrows - 1) * 32;        // last valid row-base (words)
    const int  rowb    = (wid * 32 + r) * 32;     // thread row base (words)

    const float* mods[4] = {audio, video, x1, x2};
    const uint32_t xbase = sb + XOFF + (wid * 32 + r) * 64 + q * 16;

    // ---- pipeline prologue: stages 0..3 of first tile ----
    {
        long offw0 = bid * TILEW;
        issue_ct<0>(mods, q, offw0, rowb, maxw, true, xbase + 0 * XSTAGE);
        issue_ct<1>(mods, q, offw0, rowb, maxw, true, xbase + 1 * XSTAGE);
        issue_ct<2>(mods, q, offw0, rowb, maxw, true, xbase + 2 * XSTAGE);
        issue_ct<3>(mods, q, offw0, rowb, maxw, true, xbase + 3 * XSTAGE);
    }

    // ---- weights -> fp16 smem (once per CTA; k-permuted W1, standard W2) ----
    {
        const float4* W1f4 = (const float4*)W1;   // 2048 float4
        const float4* W2f4 = (const float4*)W2;   // 1024 float4
#pragma unroll
        for (int it = 0; it < 6; it++) {
            int i = tid + it * THREADS;
            if (i < 2048) {
                float4 v = W1f4[i];
                int n = i >> 5, k4 = i & 31;
                int kb = (k4 & ~3) * 4;
                int qq = k4 & 3;
                int f0 = kb + 2 * qq;
                int f1 = kb + 2 * qq + 8;
                *(uint32_t*)(smem + OFF_W1HI + n * S_W1 + f0 * 2) = pack_f16(v.x, v.y);
                *(uint32_t*)(smem + OFF_W1HI + n * S_W1 + f1 * 2) = pack_f16(v.z, v.w);
            } else {
                int j = i - 2048;
                float4 v = W2f4[j];
                int n = j >> 4, k4 = j & 15;
                uint2 hp;
                hp.x = pack_f16(v.x, v.y);
                hp.y = pack_f16(v.z, v.w);
                *(uint2*)(smem + OFF_W2HI + n * S_W2 + k4 * 8) = hp;
            }
        }
        float* bs = (float*)(smem + OFF_BIAS);
        if (tid < 64)  bs[tid] = b1[tid];
        else if (tid < 128) bs[tid] = b2[tid - 64];
    }
    __syncthreads();

    // per-lane ldmatrix base offsets
    const int rowp = ((lane >> 4) & 1) * 8 + (lane & 7);
    const int kadd = ((lane >> 3) & 1) * 16;
    const uint32_t aW1hi = sb + OFF_W1HI + rowp * S_W1 + kadd;
    const uint32_t aW2hi = sb + OFF_W2HI + rowp * S_W2 + kadd;
    const float* b1s = (const float*)(smem + OFF_BIAS);
    const float* b2s = b1s + 64;

    int bc = 0, bi = 4;   // consume / issue buffer cursors (mod 5)

    // ================= persistent tile loop =================
    for (long tile = bid; tile < ntiles; tile += gstride) {
        const long offw_cur = tile * TILEW;
        const long tile_nxt = tile + gstride;
        const bool nxt_ok   = tile_nxt < ntiles;
        const long offw_nxt = tile_nxt * TILEW;

        float acc0[8][4], acc1[8][4];
#pragma unroll
        for (int j = 0; j < 8; j++)
#pragma unroll
            for (int i = 0; i < 4; i++) { acc0[j][i] = 0.f; acc1[j][i] = 0.f; }

#pragma unroll
        for (int kt = 0; kt < 8; kt++) {
            cp_wait3();
            const uint32_t xsrc = xbase + bc * XSTAGE;
            uint4 pv[4];
#pragma unroll
            for (int s = 0; s < 4; s++) pv[s] = lds128(xsrc + s * 512);

            // issue: kt<4 -> this tile's stage kt+4; kt>=4 -> next tile's kt-4
            const uint32_t dsti = xbase + bi * XSTAGE;
            switch (kt) {   // kt is compile-time (loop unrolled)
                case 0: issue_ct<4>(mods, q, offw_cur, rowb, maxw, true,   dsti); break;
                case 1: issue_ct<5>(mods, q, offw_cur, rowb, maxw, true,   dsti); break;
                case 2: issue_ct<6>(mods, q, offw_cur, rowb, maxw, true,   dsti); break;
                case 3: issue_ct<7>(mods, q, offw_cur, rowb, maxw, true,   dsti); break;
                case 4: issue_ct<0>(mods, q, offw_nxt, rowb, maxw, nxt_ok, dsti); break;
                case 5: issue_ct<1>(mods, q, offw_nxt, rowb, maxw, nxt_ok, dsti); break;
                case 6: issue_ct<2>(mods, q, offw_nxt, rowb, maxw, nxt_ok, dsti); break;
                case 7: issue_ct<3>(mods, q, offw_nxt, rowb, maxw, nxt_ok, dsti); break;
            }
            bc = (bc == NSTAGE - 1) ? 0 : bc + 1;
            bi = (bi == NSTAGE - 1) ? 0 : bi + 1;

            uint32_t ah0[4], ah1[4];
            ah0[0] = pack_f16(__uint_as_float(pv[0].x), __uint_as_float(pv[0].y));
            ah0[1] = pack_f16(__uint_as_float(pv[1].x), __uint_as_float(pv[1].y));
            ah0[2] = pack_f16(__uint_as_float(pv[0].z), __uint_as_float(pv[0].w));
            ah0[3] = pack_f16(__uint_as_float(pv[1].z), __uint_as_float(pv[1].w));
            ah1[0] = pack_f16(__uint_as_float(pv[2].x), __uint_as_float(pv[2].y));
            ah1[1] = pack_f16(__uint_as_float(pv[3].x), __uint_as_float(pv[3].y));
            ah1[2] = pack_f16(__uint_as_float(pv[2].z), __uint_as_float(pv[2].w));
            ah1[3] = pack_f16(__uint_as_float(pv[3].z), __uint_as_float(pv[3].w));

#pragma unroll
            for (int j = 0; j < 4; j++) {
                uint32_t bh[4];
                ldsm4(bh, aW1hi + j * (16 * S_W1) + kt * 32);
                mma_f16(acc0[2*j],   ah0, bh[0], bh[1]);
                mma_f16(acc0[2*j+1], ah0, bh[2], bh[3]);
                mma_f16(acc1[2*j],   ah1, bh[0], bh[1]);
                mma_f16(acc1[2*j+1], ah1, bh[2], bh[3]);
            }
        }

        // ---- epilogue 1: H = relu(acc + b1) -> fp16 frags ----
        uint32_t hr0[8], hr08[8], hr1[8], hr18[8];
#pragma unroll
        for (int j = 0; j < 8; j++) {
            float2 bv = *(const float2*)(b1s + j * 8 + q * 2);
            hr0[j]  = pack_f16(fmaxf(acc0[j][0] + bv.x, 0.f),
                               fmaxf(acc0[j][1] + bv.y, 0.f));
            hr08[j] = pack_f16(fmaxf(acc0[j][2] + bv.x, 0.f),
                               fmaxf(acc0[j][3] + bv.y, 0.f));
            hr1[j]  = pack_f16(fmaxf(acc1[j][0] + bv.x, 0.f),
                               fmaxf(acc1[j][1] + bv.y, 0.f));
            hr18[j] = pack_f16(fmaxf(acc1[j][2] + bv.x, 0.f),
                               fmaxf(acc1[j][3] + bv.y, 0.f));
        }

        // ---- GEMM2 (single pass) + streaming stores ----
        const long orow = tile * TM + wid * 32 + r;
        const bool tfull = (tile * TM + TM) <= nrows;
        const bool s0a = tfull || (orow      < nrows);
        const bool s0b = tfull || (orow + 8  < nrows);
        const bool s1a = tfull || (orow + 16 < nrows);
        const bool s1b = tfull || (orow + 24 < nrows);

#pragma unroll
        for (int j = 0; j < 4; j++) {
            float c0[2][4], c1[2][4];
#pragma unroll
            for (int u = 0; u < 2; u++)
#pragma unroll
                for (int i = 0; i < 4; i++) { c0[u][i] = 0.f; c1[u][i] = 0.f; }

#pragma unroll
            for (int t = 0; t < 4; t++) {
                uint32_t bh[4];
                ldsm4(bh, aW2hi + j * (16 * S_W2) + t * 32);
                uint32_t a0[4] = {hr0[2*t], hr08[2*t], hr0[2*t+1], hr08[2*t+1]};
                uint32_t a1[4] = {hr1[2*t], hr18[2*t], hr1[2*t+1], hr18[2*t+1]};
                mma_f16(c0[0], a0, bh[0], bh[1]);
                mma_f16(c0[1], a0, bh[2], bh[3]);
                mma_f16(c1[0], a1, bh[0], bh[1]);
                mma_f16(c1[1], a1, bh[2], bh[3]);
            }

#pragma unroll
            for (int u = 0; u < 2; u++) {
                int col = (2*j + u) * 8 + q * 2;
                float2 bv = *(const float2*)(b2s + col);
                if (s0a) stcs2(out + orow * 64 + col,
                               c0[u][0] + bv.x, c0[u][1] + bv.y);
                if (s0b) stcs2(out + (orow + 8) * 64 + col,
                               c0[u][2] + bv.x, c0[u][3] + bv.y);
                if (s1a) stcs2(out + (orow + 16) * 64 + col,
                               c1[u][0] + bv.x, c1[u][1] + bv.y);
                if (s1b) stcs2(out + (orow + 24) * 64 + col,
                               c1[u][2] + bv.x, c1[u][3] + bv.y);
            }
        }
    }
    cp_wait_all();

    // ---- block 0: exact fp32 fixup for graph rows 0..3 ----
    if (blockIdx.x == 0) {
        __syncthreads();                 // all warps past their tile loop
        float* xbar = (float*)smem;      // weight region is dead now
        float* h    = xbar + 128;
        const int t = tid;
        if (t < 128) {
            const float* pm = mods[t >> 5];
            int c = t & 31;
            xbar[t] = 0.25f * (pm[c] + pm[32 + c] + pm[64 + c] + pm[96 + c]);
        }
        __syncthreads();
        if (t < 64) {
            float s = 0.f;
            const float* wr = &W1[t * 128];
#pragma unroll 8
            for (int k = 0; k < 128; k++) s = fmaf(wr[k], xbar[k], s);
            h[t] = fmaxf(s + b1[t], 0.f);
        }
        __syncthreads();
        if (t < 64) {
            float s = 0.f;
            const float* wr = &W2[t * 64];
#pragma unroll 8
            for (int j = 0; j < 64; j++) s = fmaf(wr[j], h[j], s);
            float v = s + b2[t];
            out[0 * 64 + t] = v;
            out[1 * 64 + t] = v;
            out[2 * 64 + t] = v;
            out[3 * 64 + t] = v;
        }
    }
}

extern "C" void kernel_launch(void* const* d_in, const int* in_sizes, int n_in,
                              void* d_out, int out_size) {
    const float* audio = (const float*)d_in[0];
    const float* video = (const float*)d_in[1];
    const float* x1    = (const float*)d_in[2];
    const float* x2    = (const float*)d_in[3];
    const float* W1    = (const float*)d_in[4];
    const float* b1    = (const float*)d_in[5];
    const float* W2    = (const float*)d_in[6];
    const float* b2    = (const float*)d_in[7];
    float* out = (float*)d_out;

    long nrows = (long)(in_sizes[0] / 32);
    long ntiles = (nrows + TM - 1) / TM;

    static int nsm = 0;
    if (nsm == 0) {
        cudaDeviceGetAttribute(&nsm, cudaDevAttrMultiProcessorCount, 0);
        if (nsm <= 0) nsm = 148;
        cudaFuncSetAttribute(mlp_main, cudaFuncAttributeMaxDynamicSharedMemorySize,
                             SMEM_TOTAL);
    }
    int grid = (int)(ntiles < (long)nsm ? ntiles : (long)nsm);

    mlp_main<<<grid, THREADS, SMEM_TOTAL>>>(audio, video, x1, x2, W1, b1, W2, b2,
                                            out, nrows);
}